// round 6
// baseline (speedup 1.0000x reference)
#include <cuda_runtime.h>
#include <math.h>
#include <stdint.h>

// ---------------- problem constants ----------------
namespace {
constexpr int BATCH = 2;
constexpr int SEQ   = 1024;
constexpr int DIM   = 768;
constexpr int NH    = 12;
constexpr int HD    = 64;
constexpr int FFD   = 3072;
constexpr int NE    = 4;
constexpr int NTOK  = BATCH * SEQ;     // 2048
constexpr int BHZ   = BATCH * NH;      // 24
constexpr int ROWS_TOT = BHZ * SEQ;
constexpr float EPSZ  = 1e-5f;
constexpr float EPSLN = 1e-5f;
constexpr int SMEM_GEMM = 4 * (128 + 128) * 16 * 4;  // 65536 B: 4-stage ring
}

// ---------------- scratch (static device memory) ----------------
__device__ __align__(16) float g_Q[NTOK * DIM];
__device__ __align__(16) float g_K[NTOK * DIM];
__device__ __align__(16) float g_Vt[BHZ * HD * SEQ];          // V^T: [b][h][d][t]
__device__ __align__(16) float g_P[(size_t)BHZ * SEQ * SEQ];  // raw scaled logits
__device__ __align__(16) float g_attn[NTOK * DIM];
__device__ __align__(16) float g_attno[NTOK * DIM];
__device__ __align__(16) float g_x[NTOK * DIM];
__device__ __align__(16) float g_H1[(size_t)NE * NTOK * FFD];
__device__ __align__(16) float g_Y[(size_t)NE * NTOK * DIM];
__device__ float2 g_rowc[ROWS_TOT];     // (c1, c0): e = exp(p*c1 + c0)
__device__ int   g_cnt[NE];
__device__ int   g_list[NE * NTOK];
__device__ int   g_tslot[2 * NTOK];
__device__ float g_tw[2 * NTOK];

// ---------------- primitives ----------------
__device__ __forceinline__ void mma_op(float* d, const uint32_t* a, uint32_t b0, uint32_t b1) {
    asm volatile(
        "mma.sync.aligned.m16n8k8.row.col.f32.tf32.tf32.f32 "
        "{%0,%1,%2,%3},{%4,%5,%6,%7},{%8,%9},{%0,%1,%2,%3};\n"
        : "+f"(d[0]), "+f"(d[1]), "+f"(d[2]), "+f"(d[3])
        : "r"(a[0]), "r"(a[1]), "r"(a[2]), "r"(a[3]), "r"(b0), "r"(b1));
}
__device__ __forceinline__ void cp_async16(float* dst, const float* src, int sz) {
    uint32_t s = (uint32_t)__cvta_generic_to_shared(dst);
    asm volatile("cp.async.cg.shared.global [%0], [%1], 16, %2;\n"
                 :: "r"(s), "l"(src), "r"(sz));
}
// swizzled float index in a (rows x 16f) tile (A operand / NT B operand)
__device__ __forceinline__ int swz(int row, int col) {
    return (row << 4) + (((((col >> 2) ^ ((row >> 1) & 3))) << 2) | (col & 3));
}
// swizzled index in a TN B tile (16 k-rows x 128 n floats)
__device__ __forceinline__ int swzt(int k, int n) {
    return (k << 7) + ((((n >> 2) ^ ((k & 3) << 1)) << 2) | (n & 3));
}
// ordered-uint encode for float atomic max/min
__device__ __forceinline__ unsigned fenc(float f) {
    unsigned u = __float_as_uint(f);
    return (u & 0x80000000u) ? ~u : (u | 0x80000000u);
}
__device__ __forceinline__ float fdec(unsigned u) {
    unsigned b = (u & 0x80000000u) ? (u ^ 0x80000000u) : ~u;
    return __uint_as_float(b);
}

// ---------------- 4-stage cp.async tf32 MMA core: 1 sync / 2 k-chunks ----------------
// BM=128, BK=16/chunk, 256 threads. BN=128: warps 2x4, MT=4.
// BT=0: pb1/pb2 per-thread B row pointers ([N,K] K-contig).
// BT=1: pb1 = B + n0 ([K,N] N-contig), stride ldbt.
template<int BN, int BT>
__device__ __forceinline__ void mma_core4(
    const float* pa1, int sa1, const float* pa2, int sa2,
    const float* pb1, const float* pb2, int ldbt,
    int K, float* smem, float (&acc)[(BN == 128) ? 4 : 2][4][4])
{
    constexpr int MT  = (BN == 128) ? 4 : 2;
    constexpr int WN  = (BN == 128) ? 4 : 2;
    constexpr int ASZ = 128 * 16;
    constexpr int BSZ = BN * 16;
    constexpr int STG = ASZ + BSZ;
    const int tid = threadIdx.x;
    const int lane = tid & 31, wid = tid >> 5;
    const int wm = wid / WN, wn = wid % WN;
    const int gid = lane >> 2, tig = lane & 3;
    const int crow = tid >> 2, cq = tid & 3;
    const int coff  = (crow << 4) + ((cq ^ ((crow >> 1) & 3)) << 2);
    const int coff2 = ((crow + 64) << 4) + ((cq ^ ((crow >> 1) & 3)) << 2);
    const int q4 = 4 * cq;
    const int kk = tid >> 4, ng = tid & 15;           // BT mode
    const int bco1 = swzt(kk, 4 * ng);
    const int bco2 = swzt(kk, 4 * (ng + 16));

    auto issue = [&](int i) {
        float* As = smem + (i & 3) * STG;
        float* Bs = As + ASZ;
        const int kt = i << 4;
        cp_async16(As + coff,  pa1 + kt + q4, sa1);
        cp_async16(As + coff2, pa2 + kt + q4, sa2);
        if (BT) {
            const float* bp = pb1 + (size_t)(kt + kk) * ldbt;
            cp_async16(Bs + bco1, bp + 4 * ng, 16);
            cp_async16(Bs + bco2, bp + 4 * ng + 64, 16);
        } else {
            cp_async16(Bs + coff,  pb1 + kt + q4, 16);
            if (BN == 128) cp_async16(Bs + coff2, pb2 + kt + q4, 16);
        }
        asm volatile("cp.async.commit_group;\n" ::: "memory");
    };
    auto compute = [&](int s) {
        const float* As = smem + s * STG;
        const float* Bs = As + ASZ;
#pragma unroll
        for (int c = 0; c < 2; c++) {
            const int k0 = c * 8 + tig;
            uint32_t af[MT][4];
#pragma unroll
            for (int mt = 0; mt < MT; mt++) {
                const int ar = wm * (MT * 16) + mt * 16 + gid;
                af[mt][0] = __float_as_uint(As[swz(ar, k0)]);
                af[mt][1] = __float_as_uint(As[swz(ar + 8, k0)]);
                af[mt][2] = __float_as_uint(As[swz(ar, k0 + 4)]);
                af[mt][3] = __float_as_uint(As[swz(ar + 8, k0 + 4)]);
            }
#pragma unroll
            for (int nt = 0; nt < 4; nt++) {
                const int br = wn * 32 + nt * 8 + gid;
                uint32_t b0, b1;
                if (BT) {
                    b0 = __float_as_uint(Bs[swzt(k0, br)]);
                    b1 = __float_as_uint(Bs[swzt(k0 + 4, br)]);
                } else {
                    b0 = __float_as_uint(Bs[swz(br, k0)]);
                    b1 = __float_as_uint(Bs[swz(br, k0 + 4)]);
                }
#pragma unroll
                for (int mt = 0; mt < MT; mt++) mma_op(acc[mt][nt], af[mt], b0, b1);
            }
        }
    };

    const int nk = K >> 4;   // assumed even
    issue(0);
    issue(1);
    for (int i = 0; i < nk; i += 2) {
        asm volatile("cp.async.wait_group 0;\n" ::: "memory");
        __syncthreads();
        if (i + 2 < nk) issue(i + 2);
        if (i + 3 < nk) issue(i + 3);
        compute(i & 3);
        compute((i + 1) & 3);
    }
}

// ---------------- fused QKV projection (z: 0=Q,1=K,2=V-transposed) ----------------
__global__ __launch_bounds__(256, 2) void qkv_mma(
    const float* __restrict__ A,
    const float* __restrict__ Wq, const float* __restrict__ bq,
    const float* __restrict__ Wk, const float* __restrict__ bk,
    const float* __restrict__ Wv, const float* __restrict__ bv)
{
    extern __shared__ float smem[];
    const int tid = threadIdx.x;
    const int lane = tid & 31, wid = tid >> 5;
    const int wm = wid / 4, wn = wid % 4;
    const int gid = lane >> 2, tig = lane & 3;
    const int crow = tid >> 2;
    float acc[4][4][4] = {};
    const int which = blockIdx.z;
    const float* W = (which == 0) ? Wq : (which == 1) ? Wk : Wv;
    const float* bias = (which == 0) ? bq : (which == 1) ? bk : bv;
    const int m0 = blockIdx.y * 128, n0 = blockIdx.x * 128;
    mma_core4<128, 0>(A + (size_t)(m0 + crow) * DIM, 16,
                      A + (size_t)(m0 + crow + 64) * DIM, 16,
                      W + (size_t)(n0 + crow) * DIM,
                      W + (size_t)(n0 + crow + 64) * DIM, 0,
                      DIM, smem, acc);
#pragma unroll
    for (int mt = 0; mt < 4; mt++) {
#pragma unroll
        for (int nt = 0; nt < 4; nt++) {
            int row = m0 + wm * 64 + mt * 16 + gid;
            int col = n0 + wn * 32 + nt * 8 + 2 * tig;
            float c0 = acc[mt][nt][0] + bias[col];
            float c1 = acc[mt][nt][1] + bias[col + 1];
            float c2 = acc[mt][nt][2] + bias[col];
            float c3 = acc[mt][nt][3] + bias[col + 1];
            if (which == 0) {
                *(float2*)(g_Q + (size_t)row * DIM + col) = make_float2(c0, c1);
                *(float2*)(g_Q + (size_t)(row + 8) * DIM + col) = make_float2(c2, c3);
            } else if (which == 1) {
                *(float2*)(g_K + (size_t)row * DIM + col) = make_float2(c0, c1);
                *(float2*)(g_K + (size_t)(row + 8) * DIM + col) = make_float2(c2, c3);
            } else {
                float vals[4] = {c0, c1, c2, c3};
#pragma unroll
                for (int q = 0; q < 4; q++) {
                    int rr = row + (q >> 1) * 8;
                    int cc = col + (q & 1);
                    int bb = rr >> 10, tt = rr & 1023;
                    int h = cc >> 6, d = cc & 63;
                    g_Vt[(((size_t)bb * NH + h) * HD + d) * SEQ + tt] = vals[q];
                }
            }
        }
    }
}

// ---------------- O projection ----------------
__global__ __launch_bounds__(256, 2) void oproj_mma(
    const float* __restrict__ A, const float* __restrict__ W,
    const float* __restrict__ bias, float* __restrict__ C)
{
    extern __shared__ float smem[];
    const int tid = threadIdx.x;
    const int lane = tid & 31, wid = tid >> 5;
    const int wm = wid / 4, wn = wid % 4;
    const int gid = lane >> 2, tig = lane & 3;
    const int crow = tid >> 2;
    float acc[4][4][4] = {};
    const int m0 = blockIdx.y * 128, n0 = blockIdx.x * 128;
    mma_core4<128, 0>(A + (size_t)(m0 + crow) * DIM, 16,
                      A + (size_t)(m0 + crow + 64) * DIM, 16,
                      W + (size_t)(n0 + crow) * DIM,
                      W + (size_t)(n0 + crow + 64) * DIM, 0,
                      DIM, smem, acc);
#pragma unroll
    for (int mt = 0; mt < 4; mt++) {
#pragma unroll
        for (int nt = 0; nt < 4; nt++) {
            int row = m0 + wm * 64 + mt * 16 + gid;
            int col = n0 + wn * 32 + nt * 8 + 2 * tig;
            float b0 = bias[col], b1 = bias[col + 1];
            *(float2*)(C + (size_t)row * DIM + col) =
                make_float2(acc[mt][nt][0] + b0, acc[mt][nt][1] + b1);
            *(float2*)(C + (size_t)(row + 8) * DIM + col) =
                make_float2(acc[mt][nt][2] + b0, acc[mt][nt][3] + b1);
        }
    }
}

// ---------------- QK^T over full rows + local stats -> g_rowc ----------------
__global__ __launch_bounds__(256, 2) void qk_mma(
    const float* __restrict__ Q, const float* __restrict__ Kt, float scale,
    const float* __restrict__ gamma)
{
    extern __shared__ float smem[];
    __shared__ float s_sum[128], s_sq[128];
    __shared__ unsigned s_mx[128], s_mn[128];
    const int tid = threadIdx.x;
    const int lane = tid & 31, wid = tid >> 5;
    const int wm = wid / 4, wn = wid % 4;
    const int gid = lane >> 2, tig = lane & 3;
    const int crow = tid >> 2;
    const int z = blockIdx.y, b = z / NH, h = z % NH;
    const int m0 = blockIdx.x * 128;
    const float* Ab = Q + (size_t)b * SEQ * DIM + h * HD;
    const float* Bb = Kt + (size_t)b * SEQ * DIM + h * HD;
    float* Cb = g_P + (size_t)z * SEQ * SEQ;
    if (tid < 128) {
        s_sum[tid] = 0.f; s_sq[tid] = 0.f;
        s_mx[tid] = fenc(-3e38f); s_mn[tid] = fenc(3e38f);
    }
    // (first __syncthreads inside mma_core4 orders init before epilogue atomics)
    const float* pa1 = Ab + (size_t)(m0 + crow) * DIM;
    const float* pa2 = Ab + (size_t)(m0 + crow + 64) * DIM;
    for (int nblk = 0; nblk < 8; nblk++) {
        const int n0 = nblk * 128;
        float acc[4][4][4] = {};
        mma_core4<128, 0>(pa1, 16, pa2, 16,
                          Bb + (size_t)(n0 + crow) * DIM,
                          Bb + (size_t)(n0 + crow + 64) * DIM, 0,
                          HD, smem, acc);
#pragma unroll
        for (int mt = 0; mt < 4; mt++) {
            float s0 = 0.f, q0 = 0.f, s8 = 0.f, q8 = 0.f;
            float mx0 = -3e38f, mn0 = 3e38f, mx8 = -3e38f, mn8 = 3e38f;
            int lr = wm * 64 + mt * 16 + gid;
#pragma unroll
            for (int nt = 0; nt < 4; nt++) {
                int col = n0 + wn * 32 + nt * 8 + 2 * tig;
                float v0 = acc[mt][nt][0] * scale, v1 = acc[mt][nt][1] * scale;
                float v2 = acc[mt][nt][2] * scale, v3 = acc[mt][nt][3] * scale;
                *(float2*)(Cb + (size_t)(m0 + lr) * SEQ + col) = make_float2(v0, v1);
                *(float2*)(Cb + (size_t)(m0 + lr + 8) * SEQ + col) = make_float2(v2, v3);
                s0 += v0 + v1; q0 += v0 * v0 + v1 * v1;
                mx0 = fmaxf(mx0, fmaxf(v0, v1)); mn0 = fminf(mn0, fminf(v0, v1));
                s8 += v2 + v3; q8 += v2 * v2 + v3 * v3;
                mx8 = fmaxf(mx8, fmaxf(v2, v3)); mn8 = fminf(mn8, fminf(v2, v3));
            }
#pragma unroll
            for (int o = 1; o < 4; o <<= 1) {
                s0 += __shfl_xor_sync(~0u, s0, o); q0 += __shfl_xor_sync(~0u, q0, o);
                s8 += __shfl_xor_sync(~0u, s8, o); q8 += __shfl_xor_sync(~0u, q8, o);
                mx0 = fmaxf(mx0, __shfl_xor_sync(~0u, mx0, o));
                mn0 = fminf(mn0, __shfl_xor_sync(~0u, mn0, o));
                mx8 = fmaxf(mx8, __shfl_xor_sync(~0u, mx8, o));
                mn8 = fminf(mn8, __shfl_xor_sync(~0u, mn8, o));
            }
            if (tig == 0) {
                atomicAdd(&s_sum[lr], s0);  atomicAdd(&s_sq[lr], q0);
                atomicMax(&s_mx[lr], fenc(mx0)); atomicMin(&s_mn[lr], fenc(mn0));
                atomicAdd(&s_sum[lr + 8], s8); atomicAdd(&s_sq[lr + 8], q8);
                atomicMax(&s_mx[lr + 8], fenc(mx8)); atomicMin(&s_mn[lr + 8], fenc(mn8));
            }
        }
    }
    __syncthreads();
    if (tid < 128) {
        float s = s_sum[tid], q = s_sq[tid];
        float mean = s * (1.f / SEQ);
        float var = fmaxf((q - s * s * (1.f / SEQ)) * (1.f / (SEQ - 1)), 0.f);
        float c1 = (*gamma) / (sqrtf(var) + EPSZ);
        float mx = fdec(s_mx[tid]), mn = fdec(s_mn[tid]);
        float zmax = fmaxf(c1 * (mx - mean), c1 * (mn - mean));
        g_rowc[(size_t)z * SEQ + m0 + tid] = make_float2(c1, -mean * c1 - zmax);
    }
}

// ---------------- fused zscore-softmax + P@V ----------------
__global__ __launch_bounds__(256, 2) void pv2_mma()
{
    __shared__ float Asm[2][128 * 16];
    __shared__ float Bsm[3][64 * 16];
    __shared__ float denom_s[128];
    const int tid = threadIdx.x;
    const int lane = tid & 31, wid = tid >> 5;
    const int wm = wid / 2, wn = wid % 2;
    const int gid = lane >> 2, tig = lane & 3;
    const int crow = tid >> 2, cq = tid & 3;
    const int coff  = (crow << 4) + ((cq ^ ((crow >> 1) & 3)) << 2);
    const int coff2 = ((crow + 64) << 4) + ((cq ^ ((crow >> 1) & 3)) << 2);
    const int q4 = 4 * cq;
    float acc[2][4][4] = {};
    const int z = blockIdx.z, b = z / NH, h = z % NH;
    const int m0 = blockIdx.y * 128;
    const float* Arow1 = g_P + ((size_t)z * SEQ + m0 + crow) * SEQ;
    const float* Arow2 = g_P + ((size_t)z * SEQ + m0 + crow + 64) * SEQ;
    const float* Brow = g_Vt + (size_t)z * HD * SEQ + (size_t)crow * SEQ;
    const float2 rc1 = g_rowc[(size_t)z * SEQ + m0 + crow];
    const float2 rc2 = g_rowc[(size_t)z * SEQ + m0 + crow + 64];
    float esum1 = 0.f, esum2 = 0.f;
    constexpr int nk = SEQ / 16;  // 64

    auto issueB = [&](int i) {
        cp_async16(Bsm[i % 3] + coff, Brow + (i << 4) + q4, 16);
        asm volatile("cp.async.commit_group;\n" ::: "memory");
    };
    auto compute = [&](const float* As, const float* Bs) {
#pragma unroll
        for (int c = 0; c < 2; c++) {
            const int k0 = c * 8 + tig;
            uint32_t af[2][4];
#pragma unroll
            for (int mt = 0; mt < 2; mt++) {
                const int ar = wm * 32 + mt * 16 + gid;
                af[mt][0] = __float_as_uint(As[swz(ar, k0)]);
                af[mt][1] = __float_as_uint(As[swz(ar + 8, k0)]);
                af[mt][2] = __float_as_uint(As[swz(ar, k0 + 4)]);
                af[mt][3] = __float_as_uint(As[swz(ar + 8, k0 + 4)]);
            }
#pragma unroll
            for (int nt = 0; nt < 4; nt++) {
                const int br = wn * 32 + nt * 8 + gid;
                uint32_t b0 = __float_as_uint(Bs[swz(br, k0)]);
                uint32_t b1 = __float_as_uint(Bs[swz(br, k0 + 4)]);
#pragma unroll
                for (int mt = 0; mt < 2; mt++) mma_op(acc[mt][nt], af[mt], b0, b1);
            }
        }
    };

    issueB(0);
    issueB(1);
    float4 a0 = *(const float4*)(Arow1 + q4);
    float4 a1 = *(const float4*)(Arow2 + q4);
    for (int i = 0; i < nk; i++) {
        if (i + 1 < nk) asm volatile("cp.async.wait_group 1;\n" ::: "memory");
        else            asm volatile("cp.async.wait_group 0;\n" ::: "memory");
        __syncthreads();
        if (i + 2 < nk) issueB(i + 2);
        float4 e0, e1;
        e0.x = __expf(fmaf(a0.x, rc1.x, rc1.y));
        e0.y = __expf(fmaf(a0.y, rc1.x, rc1.y));
        e0.z = __expf(fmaf(a0.z, rc1.x, rc1.y));
        e0.w = __expf(fmaf(a0.w, rc1.x, rc1.y));
        e1.x = __expf(fmaf(a1.x, rc2.x, rc2.y));
        e1.y = __expf(fmaf(a1.y, rc2.x, rc2.y));
        e1.z = __expf(fmaf(a1.z, rc2.x, rc2.y));
        e1.w = __expf(fmaf(a1.w, rc2.x, rc2.y));
        esum1 += e0.x + e0.y + e0.z + e0.w;
        esum2 += e1.x + e1.y + e1.z + e1.w;
        *(float4*)(Asm[i & 1] + coff)  = e0;
        *(float4*)(Asm[i & 1] + coff2) = e1;
        if (i + 1 < nk) {
            a0 = *(const float4*)(Arow1 + ((i + 1) << 4) + q4);
            a1 = *(const float4*)(Arow2 + ((i + 1) << 4) + q4);
        }
        __syncthreads();
        compute(Asm[i & 1], Bsm[i % 3]);
    }
#pragma unroll
    for (int o = 1; o < 4; o <<= 1) {
        esum1 += __shfl_xor_sync(~0u, esum1, o);
        esum2 += __shfl_xor_sync(~0u, esum2, o);
    }
    if ((tid & 3) == 0) {
        denom_s[crow] = esum1;
        denom_s[crow + 64] = esum2;
    }
    __syncthreads();
#pragma unroll
    for (int mt = 0; mt < 2; mt++) {
#pragma unroll
        for (int nt = 0; nt < 4; nt++) {
            int ro = wm * 32 + mt * 16 + gid;
            int col = wn * 32 + nt * 8 + 2 * tig;
            float r0 = 1.f / denom_s[ro];
            float r8 = 1.f / denom_s[ro + 8];
            int row = m0 + ro;
            float* c0 = g_attn + ((size_t)(b * SEQ + row)) * DIM + h * HD + col;
            float* c1 = g_attn + ((size_t)(b * SEQ + row + 8)) * DIM + h * HD + col;
            *(float2*)c0 = make_float2(acc[mt][nt][0] * r0, acc[mt][nt][1] * r0);
            *(float2*)c1 = make_float2(acc[mt][nt][2] * r8, acc[mt][nt][3] * r8);
        }
    }
}

// ---------------- FF1 (TN): H1 = relu(x[list] @ W1[e] + b1) ----------------
__global__ __launch_bounds__(256, 2) void ff1_mma(
    const float* __restrict__ x, const float* __restrict__ W1,
    const float* __restrict__ b1)
{
    const int e = blockIdx.z;
    const int cnt = g_cnt[e];
    const int m0 = blockIdx.y * 128;
    if (m0 >= cnt) return;
    extern __shared__ float smem[];
    const int tid = threadIdx.x;
    const int lane = tid & 31, wid = tid >> 5;
    const int wm = wid / 4, wn = wid % 4;
    const int gid = lane >> 2, tig = lane & 3;
    const int crow = tid >> 2;
    float acc[4][4][4] = {};
    const int n0 = blockIdx.x * 128;
    const int r1 = m0 + crow, r2 = m0 + crow + 64;
    const float* pa1 = x; int sa1 = 0;
    const float* pa2 = x; int sa2 = 0;
    if (r1 < cnt) { pa1 = x + (size_t)g_list[e * NTOK + r1] * DIM; sa1 = 16; }
    if (r2 < cnt) { pa2 = x + (size_t)g_list[e * NTOK + r2] * DIM; sa2 = 16; }
    const float* Bb = W1 + (size_t)e * DIM * FFD + n0;
    const float* bb = b1 + e * FFD;
    float* Hout = g_H1 + (size_t)e * NTOK * FFD;
    mma_core4<128, 1>(pa1, sa1, pa2, sa2, Bb, nullptr, FFD, DIM, smem, acc);
#pragma unroll
    for (int mt = 0; mt < 4; mt++) {
#pragma unroll
        for (int nt = 0; nt < 4; nt++) {
            int lm = m0 + wm * 64 + mt * 16 + gid;
            int col = n0 + wn * 32 + nt * 8 + 2 * tig;
            float b0 = bb[col], b1v = bb[col + 1];
            if (lm < cnt) {
                *(float2*)(Hout + (size_t)lm * FFD + col) =
                    make_float2(fmaxf(acc[mt][nt][0] + b0, 0.f), fmaxf(acc[mt][nt][1] + b1v, 0.f));
            }
            if (lm + 8 < cnt) {
                *(float2*)(Hout + (size_t)(lm + 8) * FFD + col) =
                    make_float2(fmaxf(acc[mt][nt][2] + b0, 0.f), fmaxf(acc[mt][nt][3] + b1v, 0.f));
            }
        }
    }
}

// ---------------- FF2 (TN): Y = H1 @ W2[e] + b2 ----------------
__global__ __launch_bounds__(256, 2) void ff2_mma(
    const float* __restrict__ W2, const float* __restrict__ b2)
{
    const int e = blockIdx.z;
    const int cnt = g_cnt[e];
    const int m0 = blockIdx.y * 128;
    if (m0 >= cnt) return;
    extern __shared__ float smem[];
    const int tid = threadIdx.x;
    const int lane = tid & 31, wid = tid >> 5;
    const int wm = wid / 4, wn = wid % 4;
    const int gid = lane >> 2, tig = lane & 3;
    const int crow = tid >> 2;
    float acc[4][4][4] = {};
    const int n0 = blockIdx.x * 128;
    const float* Ab = g_H1 + (size_t)e * NTOK * FFD;
    const int r1 = m0 + crow, r2 = m0 + crow + 64;
    const float* pa1 = Ab; int sa1 = 0;
    const float* pa2 = Ab; int sa2 = 0;
    if (r1 < cnt) { pa1 = Ab + (size_t)r1 * FFD; sa1 = 16; }
    if (r2 < cnt) { pa2 = Ab + (size_t)r2 * FFD; sa2 = 16; }
    const float* Bb = W2 + (size_t)e * FFD * DIM + n0;
    const float* bb = b2 + e * DIM;
    float* Yout = g_Y + (size_t)e * NTOK * DIM;
    mma_core4<128, 1>(pa1, sa1, pa2, sa2, Bb, nullptr, DIM, FFD, smem, acc);
#pragma unroll
    for (int mt = 0; mt < 4; mt++) {
#pragma unroll
        for (int nt = 0; nt < 4; nt++) {
            int lm = m0 + wm * 64 + mt * 16 + gid;
            int col = n0 + wn * 32 + nt * 8 + 2 * tig;
            float b0 = bb[col], b1v = bb[col + 1];
            if (lm < cnt) {
                *(float2*)(Yout + (size_t)lm * DIM + col) =
                    make_float2(acc[mt][nt][0] + b0, acc[mt][nt][1] + b1v);
            }
            if (lm + 8 < cnt) {
                *(float2*)(Yout + (size_t)(lm + 8) * DIM + col) =
                    make_float2(acc[mt][nt][2] + b0, acc[mt][nt][3] + b1v);
            }
        }
    }
}

// ---------------- reductions ----------------
__device__ __forceinline__ float blockReduceSum(float v) {
    __shared__ float red[8];
    int lane = threadIdx.x & 31, wid = threadIdx.x >> 5;
#pragma unroll
    for (int o = 16; o > 0; o >>= 1) v += __shfl_xor_sync(0xffffffffu, v, o);
    __syncthreads();
    if (lane == 0) red[wid] = v;
    __syncthreads();
    float r = (lane < 8) ? red[lane] : 0.f;
#pragma unroll
    for (int o = 16; o > 0; o >>= 1) r += __shfl_xor_sync(0xffffffffu, r, o);
    return r;
}

// ---------------- LN1 + fused gating ----------------
__global__ void add_ln1_gate_kernel(const float* __restrict__ a, const float* __restrict__ b,
                                    const float* __restrict__ g, const float* __restrict__ be,
                                    const float* __restrict__ Wg, const float* __restrict__ bg,
                                    float* __restrict__ out) {
    int t = blockIdx.x, tid = threadIdx.x;
    const float* ar = a + (size_t)t * DIM;
    const float* br = b + (size_t)t * DIM;
    float v[3];
#pragma unroll
    for (int i = 0; i < 3; i++) v[i] = ar[tid + i * 256] + br[tid + i * 256];
    float mean = blockReduceSum(v[0] + v[1] + v[2]) * (1.f / DIM);
    float sq = 0.f;
#pragma unroll
    for (int i = 0; i < 3; i++) { v[i] -= mean; sq += v[i] * v[i]; }
    float var = blockReduceSum(sq) * (1.f / DIM);
    float r = rsqrtf(var + EPSLN);
    float xv[3];
    float gp0 = 0.f, gp1 = 0.f, gp2 = 0.f, gp3 = 0.f;
#pragma unroll
    for (int i = 0; i < 3; i++) {
        int c = tid + i * 256;
        xv[i] = v[i] * r * g[c] + be[c];
        out[(size_t)t * DIM + c] = xv[i];
        gp0 += xv[i] * Wg[c];
        gp1 += xv[i] * Wg[DIM + c];
        gp2 += xv[i] * Wg[2 * DIM + c];
        gp3 += xv[i] * Wg[3 * DIM + c];
    }
    float s0 = blockReduceSum(gp0);
    float s1 = blockReduceSum(gp1);
    float s2 = blockReduceSum(gp2);
    float s3 = blockReduceSum(gp3);
    if (tid == 0) {
        float s[4] = {s0 + bg[0], s1 + bg[1], s2 + bg[2], s3 + bg[3]};
        float mx = fmaxf(fmaxf(s[0], s[1]), fmaxf(s[2], s[3]));
        float p[4], sum = 0.f;
#pragma unroll
        for (int e = 0; e < 4; e++) { p[e] = expf(s[e] - mx); sum += p[e]; }
        float ri = 1.f / sum;
#pragma unroll
        for (int e = 0; e < 4; e++) p[e] *= ri;
        int i1 = 0;
#pragma unroll
        for (int e = 1; e < 4; e++) if (p[e] > p[i1]) i1 = e;
        int i2 = (i1 == 0) ? 1 : 0;
#pragma unroll
        for (int e = 0; e < 4; e++) if (e != i1 && p[e] > p[i2]) i2 = e;
        int slot = atomicAdd(&g_cnt[i1], 1);
        g_list[i1 * NTOK + slot] = t;
        g_tslot[t] = i1 * NTOK + slot;
        g_tw[t] = p[i1];
        slot = atomicAdd(&g_cnt[i2], 1);
        g_list[i2 * NTOK + slot] = t;
        g_tslot[NTOK + t] = i2 * NTOK + slot;
        g_tw[NTOK + t] = p[i2];
    }
}

// ---------------- LN2 + MoE combine ----------------
__global__ void add_ln2_moe_kernel(const float* __restrict__ x,
                                   const float* __restrict__ g, const float* __restrict__ be,
                                   float* __restrict__ out) {
    int t = blockIdx.x, tid = threadIdx.x;
    int s1 = g_tslot[t], s2 = g_tslot[NTOK + t];
    float w1 = g_tw[t], w2 = g_tw[NTOK + t];
    const float* y1 = g_Y + (size_t)s1 * DIM;
    const float* y2 = g_Y + (size_t)s2 * DIM;
    const float* xr = x + (size_t)t * DIM;
    float v[3];
#pragma unroll
    for (int i = 0; i < 3; i++) {
        int c = tid + i * 256;
        v[i] = xr[c] + w1 * y1[c] + w2 * y2[c];
    }
    float mean = blockReduceSum(v[0] + v[1] + v[2]) * (1.f / DIM);
    float sq = 0.f;
#pragma unroll
    for (int i = 0; i < 3; i++) { v[i] -= mean; sq += v[i] * v[i]; }
    float var = blockReduceSum(sq) * (1.f / DIM);
    float r = rsqrtf(var + EPSLN);
#pragma unroll
    for (int i = 0; i < 3; i++) {
        int c = tid + i * 256;
        out[(size_t)t * DIM + c] = v[i] * r * g[c] + be[c];
    }
}

__global__ void zero_cnt_kernel() {
    if (threadIdx.x < NE) g_cnt[threadIdx.x] = 0;
}

// ---------------- launch ----------------
extern "C" void kernel_launch(void* const* d_in, const int* in_sizes, int n_in,
                              void* d_out, int out_size) {
    const float* src  = (const float*)d_in[0];
    const float* Wq = (const float*)d_in[2];
    const float* bq = (const float*)d_in[3];
    const float* Wk = (const float*)d_in[4];
    const float* bk = (const float*)d_in[5];
    const float* Wv = (const float*)d_in[6];
    const float* bv = (const float*)d_in[7];
    const float* Wo = (const float*)d_in[8];
    const float* bo = (const float*)d_in[9];
    const float* gamma = (const float*)d_in[10];
    const float* ln1g = (const float*)d_in[11];
    const float* ln1b = (const float*)d_in[12];
    const float* ln2g = (const float*)d_in[13];
    const float* ln2b = (const float*)d_in[14];
    const float* Wg = (const float*)d_in[15];
    const float* bg = (const float*)d_in[16];
    const float* W1 = (const float*)d_in[17];
    const float* b1 = (const float*)d_in[18];
    const float* W2 = (const float*)d_in[19];
    const float* b2 = (const float*)d_in[20];
    float* out = (float*)d_out;

    float *Qp, *Kp, *attnp, *attnop, *xp;
    cudaGetSymbolAddress((void**)&Qp, g_Q);
    cudaGetSymbolAddress((void**)&Kp, g_K);
    cudaGetSymbolAddress((void**)&attnp, g_attn);
    cudaGetSymbolAddress((void**)&attnop, g_attno);
    cudaGetSymbolAddress((void**)&xp, g_x);

    static bool attr_done = false;
    if (!attr_done) {
        cudaFuncSetAttribute(qkv_mma,  cudaFuncAttributeMaxDynamicSharedMemorySize, SMEM_GEMM);
        cudaFuncSetAttribute(oproj_mma, cudaFuncAttributeMaxDynamicSharedMemorySize, SMEM_GEMM);
        cudaFuncSetAttribute(qk_mma,   cudaFuncAttributeMaxDynamicSharedMemorySize, SMEM_GEMM);
        cudaFuncSetAttribute(ff1_mma,  cudaFuncAttributeMaxDynamicSharedMemorySize, SMEM_GEMM);
        cudaFuncSetAttribute(ff2_mma,  cudaFuncAttributeMaxDynamicSharedMemorySize, SMEM_GEMM);
        attr_done = true;
    }

    zero_cnt_kernel<<<1, 32>>>();

    // fused QKV projections (V written transposed)
    qkv_mma<<<dim3(DIM / 128, NTOK / 128, 3), 256, SMEM_GEMM>>>(src, Wq, bq, Wk, bk, Wv, bv);

    // logits = scale * Q K^T over full rows; stats + rowc computed locally
    qk_mma<<<dim3(SEQ / 128, BHZ), 256, SMEM_GEMM>>>(Qp, Kp, 0.125f, gamma);

    // fused zscore+softmax+PV
    pv2_mma<<<dim3(1, SEQ / 128, BHZ), 256>>>();

    // O projection
    oproj_mma<<<dim3(DIM / 128, NTOK / 128), 256, SMEM_GEMM>>>(attnp, Wo, bo, attnop);

    // x = LN1(src + attn_out), fused gating + routing
    add_ln1_gate_kernel<<<NTOK, 256>>>(src, attnop, ln1g, ln1b, Wg, bg, xp);

    // expert FFN (sparse top-2, TN weights)
    ff1_mma<<<dim3(FFD / 128, NTOK / 128, NE), 256, SMEM_GEMM>>>(xp, W1, b1);
    ff2_mma<<<dim3(DIM / 128, NTOK / 128, NE), 256, SMEM_GEMM>>>(W2, b2);

    // out = LN2(x + combine(Y))
    add_ln2_moe_kernel<<<NTOK, 256>>>(xp, ln2g, ln2b, out);
}

// round 7
// speedup vs baseline: 1.0577x; 1.0577x over previous
#include <cuda_runtime.h>
#include <math.h>
#include <stdint.h>

// ---------------- problem constants ----------------
namespace {
constexpr int BATCH = 2;
constexpr int SEQ   = 1024;
constexpr int DIM   = 768;
constexpr int NH    = 12;
constexpr int HD    = 64;
constexpr int FFD   = 3072;
constexpr int NE    = 4;
constexpr int NTOK  = BATCH * SEQ;     // 2048
constexpr int BHZ   = BATCH * NH;      // 24
constexpr int ROWS_TOT = BHZ * SEQ;    // 24576 attention rows
constexpr float EPSZ  = 1e-5f;
constexpr float EPSLN = 1e-5f;
}

// ---------------- scratch (static device memory) ----------------
__device__ __align__(16) float g_Q[NTOK * DIM];
__device__ __align__(16) float g_K[NTOK * DIM];
__device__ __align__(16) float g_Vt[BHZ * HD * SEQ];          // V^T: [b][h][d][t]
__device__ __align__(16) float g_P[(size_t)BHZ * SEQ * SEQ];  // raw scaled logits
__device__ __align__(16) float g_attn[NTOK * DIM];
__device__ __align__(16) float g_attno[NTOK * DIM];
__device__ __align__(16) float g_x[NTOK * DIM];
__device__ __align__(16) float g_H1[(size_t)NE * NTOK * FFD];
__device__ __align__(16) float g_Y[(size_t)NE * NTOK * DIM];
__device__ float g_rsum[ROWS_TOT];
__device__ float g_rsumsq[ROWS_TOT];
__device__ unsigned g_rmaxe[ROWS_TOT];
__device__ unsigned g_rmine[ROWS_TOT];
__device__ float2 g_rowc[ROWS_TOT];     // (c1, c0): e = exp(p*c1 + c0)
__device__ int   g_cnt[NE];
__device__ int   g_list[NE * NTOK];
__device__ int   g_tslot[2 * NTOK];
__device__ float g_tw[2 * NTOK];

// ---------------- primitives ----------------
__device__ __forceinline__ void mma_op(float* d, const uint32_t* a, uint32_t b0, uint32_t b1) {
    asm volatile(
        "mma.sync.aligned.m16n8k8.row.col.f32.tf32.tf32.f32 "
        "{%0,%1,%2,%3},{%4,%5,%6,%7},{%8,%9},{%0,%1,%2,%3};\n"
        : "+f"(d[0]), "+f"(d[1]), "+f"(d[2]), "+f"(d[3])
        : "r"(a[0]), "r"(a[1]), "r"(a[2]), "r"(a[3]), "r"(b0), "r"(b1));
}
__device__ __forceinline__ void cp_async16(float* dst, const float* src, int sz) {
    uint32_t s = (uint32_t)__cvta_generic_to_shared(dst);
    asm volatile("cp.async.cg.shared.global [%0], [%1], 16, %2;\n"
                 :: "r"(s), "l"(src), "r"(sz));
}
// swizzled float index in a (rows x 16f) tile (A operand / NT B operand)
__device__ __forceinline__ int swz(int row, int col) {
    return (row << 4) + (((((col >> 2) ^ ((row >> 1) & 3))) << 2) | (col & 3));
}
// swizzled index in a TN B tile (16 k-rows x 128 n floats)
__device__ __forceinline__ int swzt(int k, int n) {
    return (k << 7) + ((((n >> 2) ^ ((k & 3) << 1)) << 2) | (n & 3));
}
// ordered-uint encode for float atomic max/min
__device__ __forceinline__ unsigned fenc(float f) {
    unsigned u = __float_as_uint(f);
    return (u & 0x80000000u) ? ~u : (u | 0x80000000u);
}
__device__ __forceinline__ float fdec(unsigned u) {
    unsigned b = (u & 0x80000000u) ? (u ^ 0x80000000u) : ~u;
    return __uint_as_float(b);
}

// ---------------- cp.async 3-stage pipelined tf32 MMA core ----------------
// BM=128, BK=16, 256 threads. BN=128: warps 2x4, MT=4. BN=64: warps 4x2, MT=2.
// BT=0: pb1/pb2 per-thread B row pointers ([N,K] K-contig).
// BT=1: pb1 = B + n0 ([K,N] N-contig), stride ldbt.
template<int BN, int BT>
__device__ __forceinline__ void mma_core(
    const float* pa1, int sa1, const float* pa2, int sa2,
    const float* pb1, const float* pb2, int ldbt,
    int K, float* smem, float (&acc)[(BN == 128) ? 4 : 2][4][4])
{
    constexpr int MT  = (BN == 128) ? 4 : 2;
    constexpr int WN  = (BN == 128) ? 4 : 2;
    constexpr int ASZ = 128 * 16;
    constexpr int BSZ = BN * 16;
    constexpr int STG = ASZ + BSZ;
    const int tid = threadIdx.x;
    const int lane = tid & 31, wid = tid >> 5;
    const int wm = wid / WN, wn = wid % WN;
    const int gid = lane >> 2, tig = lane & 3;
    const int crow = tid >> 2, cq = tid & 3;
    const int coff  = (crow << 4) + ((cq ^ ((crow >> 1) & 3)) << 2);
    const int coff2 = ((crow + 64) << 4) + ((cq ^ ((crow >> 1) & 3)) << 2);
    const int q4 = 4 * cq;
    const int kk = tid >> 4, ng = tid & 15;           // BT mode
    const int bco1 = swzt(kk, 4 * ng);
    const int bco2 = swzt(kk, 4 * (ng + 16));

    auto issue = [&](int i) {
        float* As = smem + (i % 3) * STG;
        float* Bs = As + ASZ;
        const int kt = i << 4;
        cp_async16(As + coff,  pa1 + kt + q4, sa1);
        cp_async16(As + coff2, pa2 + kt + q4, sa2);
        if (BT) {
            const float* bp = pb1 + (size_t)(kt + kk) * ldbt;
            cp_async16(Bs + bco1, bp + 4 * ng, 16);
            cp_async16(Bs + bco2, bp + 4 * ng + 64, 16);
        } else {
            cp_async16(Bs + coff,  pb1 + kt + q4, 16);
            if (BN == 128) cp_async16(Bs + coff2, pb2 + kt + q4, 16);
        }
        asm volatile("cp.async.commit_group;\n" ::: "memory");
    };
    auto compute = [&](int s) {
        const float* As = smem + s * STG;
        const float* Bs = As + ASZ;
#pragma unroll
        for (int c = 0; c < 2; c++) {
            const int k0 = c * 8 + tig;
            uint32_t af[MT][4];
#pragma unroll
            for (int mt = 0; mt < MT; mt++) {
                const int ar = wm * (MT * 16) + mt * 16 + gid;
                af[mt][0] = __float_as_uint(As[swz(ar, k0)]);
                af[mt][1] = __float_as_uint(As[swz(ar + 8, k0)]);
                af[mt][2] = __float_as_uint(As[swz(ar, k0 + 4)]);
                af[mt][3] = __float_as_uint(As[swz(ar + 8, k0 + 4)]);
            }
#pragma unroll
            for (int nt = 0; nt < 4; nt++) {
                const int br = wn * 32 + nt * 8 + gid;
                uint32_t b0, b1;
                if (BT) {
                    b0 = __float_as_uint(Bs[swzt(k0, br)]);
                    b1 = __float_as_uint(Bs[swzt(k0 + 4, br)]);
                } else {
                    b0 = __float_as_uint(Bs[swz(br, k0)]);
                    b1 = __float_as_uint(Bs[swz(br, k0 + 4)]);
                }
#pragma unroll
                for (int mt = 0; mt < MT; mt++) mma_op(acc[mt][nt], af[mt], b0, b1);
            }
        }
    };

    const int nk = K >> 4;
    issue(0);
    if (nk > 1) issue(1);
    for (int i = 0; i < nk; i++) {
        if (i + 1 < nk) asm volatile("cp.async.wait_group 1;\n" ::: "memory");
        else            asm volatile("cp.async.wait_group 0;\n" ::: "memory");
        __syncthreads();
        if (i + 2 < nk) issue(i + 2);
        compute(i % 3);
    }
}

// ---------------- fused QKV projection (z: 0=Q,1=K,2=V-transposed) ----------------
__global__ __launch_bounds__(256, 2) void qkv_mma(
    const float* __restrict__ A,
    const float* __restrict__ Wq, const float* __restrict__ bq,
    const float* __restrict__ Wk, const float* __restrict__ bk,
    const float* __restrict__ Wv, const float* __restrict__ bv)
{
    __shared__ float smem[3 * (128 * 16 + 128 * 16)];
    const int tid = threadIdx.x;
    const int lane = tid & 31, wid = tid >> 5;
    const int wm = wid / 4, wn = wid % 4;
    const int gid = lane >> 2, tig = lane & 3;
    const int crow = tid >> 2;
    float acc[4][4][4] = {};
    const int which = blockIdx.z;
    const float* W = (which == 0) ? Wq : (which == 1) ? Wk : Wv;
    const float* bias = (which == 0) ? bq : (which == 1) ? bk : bv;
    const int m0 = blockIdx.y * 128, n0 = blockIdx.x * 128;
    mma_core<128, 0>(A + (size_t)(m0 + crow) * DIM, 16,
                     A + (size_t)(m0 + crow + 64) * DIM, 16,
                     W + (size_t)(n0 + crow) * DIM,
                     W + (size_t)(n0 + crow + 64) * DIM, 0,
                     DIM, smem, acc);
#pragma unroll
    for (int mt = 0; mt < 4; mt++) {
#pragma unroll
        for (int nt = 0; nt < 4; nt++) {
            int row = m0 + wm * 64 + mt * 16 + gid;
            int col = n0 + wn * 32 + nt * 8 + 2 * tig;
            float c0 = acc[mt][nt][0] + bias[col];
            float c1 = acc[mt][nt][1] + bias[col + 1];
            float c2 = acc[mt][nt][2] + bias[col];
            float c3 = acc[mt][nt][3] + bias[col + 1];
            if (which == 0) {
                *(float2*)(g_Q + (size_t)row * DIM + col) = make_float2(c0, c1);
                *(float2*)(g_Q + (size_t)(row + 8) * DIM + col) = make_float2(c2, c3);
            } else if (which == 1) {
                *(float2*)(g_K + (size_t)row * DIM + col) = make_float2(c0, c1);
                *(float2*)(g_K + (size_t)(row + 8) * DIM + col) = make_float2(c2, c3);
            } else {
                float vals[4] = {c0, c1, c2, c3};
#pragma unroll
                for (int q = 0; q < 4; q++) {
                    int rr = row + (q >> 1) * 8;
                    int cc = col + (q & 1);
                    int bb = rr >> 10, tt = rr & 1023;
                    int h = cc >> 6, d = cc & 63;
                    g_Vt[(((size_t)bb * NH + h) * HD + d) * SEQ + tt] = vals[q];
                }
            }
        }
    }
}

// ---------------- O projection ----------------
__global__ __launch_bounds__(256, 2) void oproj_mma(
    const float* __restrict__ A, const float* __restrict__ W,
    const float* __restrict__ bias, float* __restrict__ C)
{
    __shared__ float smem[3 * (128 * 16 + 128 * 16)];
    const int tid = threadIdx.x;
    const int lane = tid & 31, wid = tid >> 5;
    const int wm = wid / 4, wn = wid % 4;
    const int gid = lane >> 2, tig = lane & 3;
    const int crow = tid >> 2;
    float acc[4][4][4] = {};
    const int m0 = blockIdx.y * 128, n0 = blockIdx.x * 128;
    mma_core<128, 0>(A + (size_t)(m0 + crow) * DIM, 16,
                     A + (size_t)(m0 + crow + 64) * DIM, 16,
                     W + (size_t)(n0 + crow) * DIM,
                     W + (size_t)(n0 + crow + 64) * DIM, 0,
                     DIM, smem, acc);
#pragma unroll
    for (int mt = 0; mt < 4; mt++) {
#pragma unroll
        for (int nt = 0; nt < 4; nt++) {
            int row = m0 + wm * 64 + mt * 16 + gid;
            int col = n0 + wn * 32 + nt * 8 + 2 * tig;
            float b0 = bias[col], b1 = bias[col + 1];
            *(float2*)(C + (size_t)row * DIM + col) =
                make_float2(acc[mt][nt][0] + b0, acc[mt][nt][1] + b1);
            *(float2*)(C + (size_t)(row + 8) * DIM + col) =
                make_float2(acc[mt][nt][2] + b0, acc[mt][nt][3] + b1);
        }
    }
}

// ---------------- QK^T + per-row stats epilogue ----------------
__global__ __launch_bounds__(256, 2) void qk_mma(
    const float* __restrict__ Q, const float* __restrict__ Kt, float scale)
{
    __shared__ float smem[3 * (128 * 16 + 128 * 16)];
    const int tid = threadIdx.x;
    const int lane = tid & 31, wid = tid >> 5;
    const int wm = wid / 4, wn = wid % 4;
    const int gid = lane >> 2, tig = lane & 3;
    const int crow = tid >> 2;
    float acc[4][4][4] = {};
    const int z = blockIdx.z, b = z / NH, h = z % NH;
    const int m0 = blockIdx.y * 128, n0 = blockIdx.x * 128;
    const float* Ab = Q + (size_t)b * SEQ * DIM + h * HD;
    const float* Bb = Kt + (size_t)b * SEQ * DIM + h * HD;
    float* Cb = g_P + (size_t)z * SEQ * SEQ;
    mma_core<128, 0>(Ab + (size_t)(m0 + crow) * DIM, 16,
                     Ab + (size_t)(m0 + crow + 64) * DIM, 16,
                     Bb + (size_t)(n0 + crow) * DIM,
                     Bb + (size_t)(n0 + crow + 64) * DIM, 0,
                     HD, smem, acc);
    const size_t rowbase = (size_t)z * SEQ + m0;
#pragma unroll
    for (int mt = 0; mt < 4; mt++) {
        float s0 = 0.f, q0 = 0.f, s8 = 0.f, q8 = 0.f;
        float mx0 = -3e38f, mn0 = 3e38f, mx8 = -3e38f, mn8 = 3e38f;
#pragma unroll
        for (int nt = 0; nt < 4; nt++) {
            int row = m0 + wm * 64 + mt * 16 + gid;
            int col = n0 + wn * 32 + nt * 8 + 2 * tig;
            float v0 = acc[mt][nt][0] * scale, v1 = acc[mt][nt][1] * scale;
            float v2 = acc[mt][nt][2] * scale, v3 = acc[mt][nt][3] * scale;
            *(float2*)(Cb + (size_t)row * SEQ + col) = make_float2(v0, v1);
            *(float2*)(Cb + (size_t)(row + 8) * SEQ + col) = make_float2(v2, v3);
            s0 += v0 + v1; q0 += v0 * v0 + v1 * v1;
            mx0 = fmaxf(mx0, fmaxf(v0, v1)); mn0 = fminf(mn0, fminf(v0, v1));
            s8 += v2 + v3; q8 += v2 * v2 + v3 * v3;
            mx8 = fmaxf(mx8, fmaxf(v2, v3)); mn8 = fminf(mn8, fminf(v2, v3));
        }
#pragma unroll
        for (int o = 1; o < 4; o <<= 1) {
            s0 += __shfl_xor_sync(~0u, s0, o); q0 += __shfl_xor_sync(~0u, q0, o);
            s8 += __shfl_xor_sync(~0u, s8, o); q8 += __shfl_xor_sync(~0u, q8, o);
            mx0 = fmaxf(mx0, __shfl_xor_sync(~0u, mx0, o));
            mn0 = fminf(mn0, __shfl_xor_sync(~0u, mn0, o));
            mx8 = fmaxf(mx8, __shfl_xor_sync(~0u, mx8, o));
            mn8 = fminf(mn8, __shfl_xor_sync(~0u, mn8, o));
        }
        if (tig == 0) {
            size_t r0 = rowbase + wm * 64 + mt * 16 + gid;
            atomicAdd(&g_rsum[r0], s0);   atomicAdd(&g_rsumsq[r0], q0);
            atomicMax(&g_rmaxe[r0], fenc(mx0)); atomicMin(&g_rmine[r0], fenc(mn0));
            atomicAdd(&g_rsum[r0 + 8], s8); atomicAdd(&g_rsumsq[r0 + 8], q8);
            atomicMax(&g_rmaxe[r0 + 8], fenc(mx8)); atomicMin(&g_rmine[r0 + 8], fenc(mn8));
        }
    }
}

// ---------------- finalize per-row zscore coefficients ----------------
__global__ void finalize_rows(const float* __restrict__ gamma) {
    int i = blockIdx.x * 256 + threadIdx.x;
    if (i >= ROWS_TOT) return;
    float s = g_rsum[i], q = g_rsumsq[i];
    float mean = s * (1.f / SEQ);
    float var = fmaxf((q - s * s * (1.f / SEQ)) * (1.f / (SEQ - 1)), 0.f);
    float c1 = (*gamma) / (sqrtf(var) + EPSZ);
    float mx = fdec(g_rmaxe[i]), mn = fdec(g_rmine[i]);
    float zmax = fmaxf(c1 * (mx - mean), c1 * (mn - mean));
    g_rowc[i] = make_float2(c1, -mean * c1 - zmax);
}

// ---------------- zero stats + routing counters ----------------
__global__ void zero_stats_kernel() {
    int i = blockIdx.x * 256 + threadIdx.x;
    if (i < ROWS_TOT) {
        g_rsum[i] = 0.f;
        g_rsumsq[i] = 0.f;
        g_rmaxe[i] = fenc(-3e38f);
        g_rmine[i] = fenc(3e38f);
    }
    if (i < NE) g_cnt[i] = 0;
}

// ---------------- fused zscore-softmax + P@V ----------------
// A = exp(c1*logit + c0) built on the fly; denom applied to MMA output.
__global__ __launch_bounds__(256, 2) void pv2_mma()
{
    __shared__ float Asm[2][128 * 16];
    __shared__ float Bsm[3][64 * 16];
    __shared__ float denom_s[128];
    const int tid = threadIdx.x;
    const int lane = tid & 31, wid = tid >> 5;
    const int wm = wid / 2, wn = wid % 2;
    const int gid = lane >> 2, tig = lane & 3;
    const int crow = tid >> 2, cq = tid & 3;
    const int coff  = (crow << 4) + ((cq ^ ((crow >> 1) & 3)) << 2);
    const int coff2 = ((crow + 64) << 4) + ((cq ^ ((crow >> 1) & 3)) << 2);
    const int q4 = 4 * cq;
    float acc[2][4][4] = {};
    const int z = blockIdx.z, b = z / NH, h = z % NH;
    const int m0 = blockIdx.y * 128;
    const float* Arow1 = g_P + ((size_t)z * SEQ + m0 + crow) * SEQ;
    const float* Arow2 = g_P + ((size_t)z * SEQ + m0 + crow + 64) * SEQ;
    const float* Brow = g_Vt + (size_t)z * HD * SEQ + (size_t)crow * SEQ;
    const float2 rc1 = g_rowc[(size_t)z * SEQ + m0 + crow];
    const float2 rc2 = g_rowc[(size_t)z * SEQ + m0 + crow + 64];
    float esum1 = 0.f, esum2 = 0.f;
    constexpr int nk = SEQ / 16;  // 64

    auto issueB = [&](int i) {
        cp_async16(Bsm[i % 3] + coff, Brow + (i << 4) + q4, 16);
        asm volatile("cp.async.commit_group;\n" ::: "memory");
    };
    auto compute = [&](const float* As, const float* Bs) {
#pragma unroll
        for (int c = 0; c < 2; c++) {
            const int k0 = c * 8 + tig;
            uint32_t af[2][4];
#pragma unroll
            for (int mt = 0; mt < 2; mt++) {
                const int ar = wm * 32 + mt * 16 + gid;
                af[mt][0] = __float_as_uint(As[swz(ar, k0)]);
                af[mt][1] = __float_as_uint(As[swz(ar + 8, k0)]);
                af[mt][2] = __float_as_uint(As[swz(ar, k0 + 4)]);
                af[mt][3] = __float_as_uint(As[swz(ar + 8, k0 + 4)]);
            }
#pragma unroll
            for (int nt = 0; nt < 4; nt++) {
                const int br = wn * 32 + nt * 8 + gid;
                uint32_t b0 = __float_as_uint(Bs[swz(br, k0)]);
                uint32_t b1 = __float_as_uint(Bs[swz(br, k0 + 4)]);
#pragma unroll
                for (int mt = 0; mt < 2; mt++) mma_op(acc[mt][nt], af[mt], b0, b1);
            }
        }
    };

    issueB(0);
    issueB(1);
    // 2-deep register prefetch of raw logit chunks
    float4 a0p[2], a1p[2];
    a0p[0] = *(const float4*)(Arow1 + q4);
    a1p[0] = *(const float4*)(Arow2 + q4);
    a0p[1] = *(const float4*)(Arow1 + 16 + q4);
    a1p[1] = *(const float4*)(Arow2 + 16 + q4);
    for (int i = 0; i < nk; i++) {
        if (i + 1 < nk) asm volatile("cp.async.wait_group 1;\n" ::: "memory");
        else            asm volatile("cp.async.wait_group 0;\n" ::: "memory");
        __syncthreads();                       // B(i) visible; compute(i-1) done
        if (i + 2 < nk) issueB(i + 2);
        float4 a0 = a0p[i & 1], a1 = a1p[i & 1];
        float4 e0, e1;
        e0.x = __expf(fmaf(a0.x, rc1.x, rc1.y));
        e0.y = __expf(fmaf(a0.y, rc1.x, rc1.y));
        e0.z = __expf(fmaf(a0.z, rc1.x, rc1.y));
        e0.w = __expf(fmaf(a0.w, rc1.x, rc1.y));
        e1.x = __expf(fmaf(a1.x, rc2.x, rc2.y));
        e1.y = __expf(fmaf(a1.y, rc2.x, rc2.y));
        e1.z = __expf(fmaf(a1.z, rc2.x, rc2.y));
        e1.w = __expf(fmaf(a1.w, rc2.x, rc2.y));
        esum1 += e0.x + e0.y + e0.z + e0.w;
        esum2 += e1.x + e1.y + e1.z + e1.w;
        *(float4*)(Asm[i & 1] + coff)  = e0;
        *(float4*)(Asm[i & 1] + coff2) = e1;
        if (i + 2 < nk) {                      // prefetch chunk i+2 (2-iter window)
            a0p[i & 1] = *(const float4*)(Arow1 + ((i + 2) << 4) + q4);
            a1p[i & 1] = *(const float4*)(Arow2 + ((i + 2) << 4) + q4);
        }
        __syncthreads();                       // A STS visible
        compute(Asm[i & 1], Bsm[i % 3]);
    }
    // row exp-sums -> denominators
#pragma unroll
    for (int o = 1; o < 4; o <<= 1) {
        esum1 += __shfl_xor_sync(~0u, esum1, o);
        esum2 += __shfl_xor_sync(~0u, esum2, o);
    }
    if ((tid & 3) == 0) {
        denom_s[crow] = esum1;
        denom_s[crow + 64] = esum2;
    }
    __syncthreads();
#pragma unroll
    for (int mt = 0; mt < 2; mt++) {
#pragma unroll
        for (int nt = 0; nt < 4; nt++) {
            int ro = wm * 32 + mt * 16 + gid;
            int col = wn * 32 + nt * 8 + 2 * tig;
            float r0 = 1.f / denom_s[ro];
            float r8 = 1.f / denom_s[ro + 8];
            int row = m0 + ro;
            float* c0 = g_attn + ((size_t)(b * SEQ + row)) * DIM + h * HD + col;
            float* c1 = g_attn + ((size_t)(b * SEQ + row + 8)) * DIM + h * HD + col;
            *(float2*)c0 = make_float2(acc[mt][nt][0] * r0, acc[mt][nt][1] * r0);
            *(float2*)c1 = make_float2(acc[mt][nt][2] * r8, acc[mt][nt][3] * r8);
        }
    }
}

// ---------------- FF1 (TN): H1 = relu(x[list] @ W1[e] + b1) ----------------
__global__ __launch_bounds__(256, 2) void ff1_mma(
    const float* __restrict__ x, const float* __restrict__ W1,
    const float* __restrict__ b1)
{
    const int e = blockIdx.z;
    const int cnt = g_cnt[e];
    const int m0 = blockIdx.y * 128;
    if (m0 >= cnt) return;
    __shared__ float smem[3 * (128 * 16 + 128 * 16)];
    const int tid = threadIdx.x;
    const int lane = tid & 31, wid = tid >> 5;
    const int wm = wid / 4, wn = wid % 4;
    const int gid = lane >> 2, tig = lane & 3;
    const int crow = tid >> 2;
    float acc[4][4][4] = {};
    const int n0 = blockIdx.x * 128;
    const int r1 = m0 + crow, r2 = m0 + crow + 64;
    const float* pa1 = x; int sa1 = 0;
    const float* pa2 = x; int sa2 = 0;
    if (r1 < cnt) { pa1 = x + (size_t)g_list[e * NTOK + r1] * DIM; sa1 = 16; }
    if (r2 < cnt) { pa2 = x + (size_t)g_list[e * NTOK + r2] * DIM; sa2 = 16; }
    const float* Bb = W1 + (size_t)e * DIM * FFD + n0;   // [K=DIM][N=FFD]
    const float* bb = b1 + e * FFD;
    float* Hout = g_H1 + (size_t)e * NTOK * FFD;
    mma_core<128, 1>(pa1, sa1, pa2, sa2, Bb, nullptr, FFD, DIM, smem, acc);
#pragma unroll
    for (int mt = 0; mt < 4; mt++) {
#pragma unroll
        for (int nt = 0; nt < 4; nt++) {
            int lm = m0 + wm * 64 + mt * 16 + gid;
            int col = n0 + wn * 32 + nt * 8 + 2 * tig;
            float b0 = bb[col], b1v = bb[col + 1];
            if (lm < cnt) {
                *(float2*)(Hout + (size_t)lm * FFD + col) =
                    make_float2(fmaxf(acc[mt][nt][0] + b0, 0.f), fmaxf(acc[mt][nt][1] + b1v, 0.f));
            }
            if (lm + 8 < cnt) {
                *(float2*)(Hout + (size_t)(lm + 8) * FFD + col) =
                    make_float2(fmaxf(acc[mt][nt][2] + b0, 0.f), fmaxf(acc[mt][nt][3] + b1v, 0.f));
            }
        }
    }
}

// ---------------- FF2 (TN): Y = H1 @ W2[e] + b2 ----------------
__global__ __launch_bounds__(256, 2) void ff2_mma(
    const float* __restrict__ W2, const float* __restrict__ b2)
{
    const int e = blockIdx.z;
    const int cnt = g_cnt[e];
    const int m0 = blockIdx.y * 128;
    if (m0 >= cnt) return;
    __shared__ float smem[3 * (128 * 16 + 128 * 16)];
    const int tid = threadIdx.x;
    const int lane = tid & 31, wid = tid >> 5;
    const int wm = wid / 4, wn = wid % 4;
    const int gid = lane >> 2, tig = lane & 3;
    const int crow = tid >> 2;
    float acc[4][4][4] = {};
    const int n0 = blockIdx.x * 128;
    const float* Ab = g_H1 + (size_t)e * NTOK * FFD;
    const int r1 = m0 + crow, r2 = m0 + crow + 64;
    const float* pa1 = Ab; int sa1 = 0;
    const float* pa2 = Ab; int sa2 = 0;
    if (r1 < cnt) { pa1 = Ab + (size_t)r1 * FFD; sa1 = 16; }
    if (r2 < cnt) { pa2 = Ab + (size_t)r2 * FFD; sa2 = 16; }
    const float* Bb = W2 + (size_t)e * FFD * DIM + n0;   // [K=FFD][N=DIM]
    const float* bb = b2 + e * DIM;
    float* Yout = g_Y + (size_t)e * NTOK * DIM;
    mma_core<128, 1>(pa1, sa1, pa2, sa2, Bb, nullptr, DIM, FFD, smem, acc);
#pragma unroll
    for (int mt = 0; mt < 4; mt++) {
#pragma unroll
        for (int nt = 0; nt < 4; nt++) {
            int lm = m0 + wm * 64 + mt * 16 + gid;
            int col = n0 + wn * 32 + nt * 8 + 2 * tig;
            float b0 = bb[col], b1v = bb[col + 1];
            if (lm < cnt) {
                *(float2*)(Yout + (size_t)lm * DIM + col) =
                    make_float2(acc[mt][nt][0] + b0, acc[mt][nt][1] + b1v);
            }
            if (lm + 8 < cnt) {
                *(float2*)(Yout + (size_t)(lm + 8) * DIM + col) =
                    make_float2(acc[mt][nt][2] + b0, acc[mt][nt][3] + b1v);
            }
        }
    }
}

// ---------------- reductions ----------------
__device__ __forceinline__ float blockReduceSum(float v) {
    __shared__ float red[8];
    int lane = threadIdx.x & 31, wid = threadIdx.x >> 5;
#pragma unroll
    for (int o = 16; o > 0; o >>= 1) v += __shfl_xor_sync(0xffffffffu, v, o);
    __syncthreads();
    if (lane == 0) red[wid] = v;
    __syncthreads();
    float r = (lane < 8) ? red[lane] : 0.f;
#pragma unroll
    for (int o = 16; o > 0; o >>= 1) r += __shfl_xor_sync(0xffffffffu, r, o);
    return r;
}

// ---------------- LN1 + fused gating ----------------
__global__ void add_ln1_gate_kernel(const float* __restrict__ a, const float* __restrict__ b,
                                    const float* __restrict__ g, const float* __restrict__ be,
                                    const float* __restrict__ Wg, const float* __restrict__ bg,
                                    float* __restrict__ out) {
    int t = blockIdx.x, tid = threadIdx.x;
    const float* ar = a + (size_t)t * DIM;
    const float* br = b + (size_t)t * DIM;
    float v[3];
#pragma unroll
    for (int i = 0; i < 3; i++) v[i] = ar[tid + i * 256] + br[tid + i * 256];
    float mean = blockReduceSum(v[0] + v[1] + v[2]) * (1.f / DIM);
    float sq = 0.f;
#pragma unroll
    for (int i = 0; i < 3; i++) { v[i] -= mean; sq += v[i] * v[i]; }
    float var = blockReduceSum(sq) * (1.f / DIM);
    float r = rsqrtf(var + EPSLN);
    float xv[3];
    float gp0 = 0.f, gp1 = 0.f, gp2 = 0.f, gp3 = 0.f;
#pragma unroll
    for (int i = 0; i < 3; i++) {
        int c = tid + i * 256;
        xv[i] = v[i] * r * g[c] + be[c];
        out[(size_t)t * DIM + c] = xv[i];
        gp0 += xv[i] * Wg[c];
        gp1 += xv[i] * Wg[DIM + c];
        gp2 += xv[i] * Wg[2 * DIM + c];
        gp3 += xv[i] * Wg[3 * DIM + c];
    }
    float s0 = blockReduceSum(gp0);
    float s1 = blockReduceSum(gp1);
    float s2 = blockReduceSum(gp2);
    float s3 = blockReduceSum(gp3);
    if (tid == 0) {
        float s[4] = {s0 + bg[0], s1 + bg[1], s2 + bg[2], s3 + bg[3]};
        float mx = fmaxf(fmaxf(s[0], s[1]), fmaxf(s[2], s[3]));
        float p[4], sum = 0.f;
#pragma unroll
        for (int e = 0; e < 4; e++) { p[e] = expf(s[e] - mx); sum += p[e]; }
        float ri = 1.f / sum;
#pragma unroll
        for (int e = 0; e < 4; e++) p[e] *= ri;
        int i1 = 0;
#pragma unroll
        for (int e = 1; e < 4; e++) if (p[e] > p[i1]) i1 = e;
        int i2 = (i1 == 0) ? 1 : 0;
#pragma unroll
        for (int e = 0; e < 4; e++) if (e != i1 && p[e] > p[i2]) i2 = e;
        int slot = atomicAdd(&g_cnt[i1], 1);
        g_list[i1 * NTOK + slot] = t;
        g_tslot[t] = i1 * NTOK + slot;
        g_tw[t] = p[i1];
        slot = atomicAdd(&g_cnt[i2], 1);
        g_list[i2 * NTOK + slot] = t;
        g_tslot[NTOK + t] = i2 * NTOK + slot;
        g_tw[NTOK + t] = p[i2];
    }
}

// ---------------- LN2 + MoE combine ----------------
__global__ void add_ln2_moe_kernel(const float* __restrict__ x,
                                   const float* __restrict__ g, const float* __restrict__ be,
                                   float* __restrict__ out) {
    int t = blockIdx.x, tid = threadIdx.x;
    int s1 = g_tslot[t], s2 = g_tslot[NTOK + t];
    float w1 = g_tw[t], w2 = g_tw[NTOK + t];
    const float* y1 = g_Y + (size_t)s1 * DIM;
    const float* y2 = g_Y + (size_t)s2 * DIM;
    const float* xr = x + (size_t)t * DIM;
    float v[3];
#pragma unroll
    for (int i = 0; i < 3; i++) {
        int c = tid + i * 256;
        v[i] = xr[c] + w1 * y1[c] + w2 * y2[c];
    }
    float mean = blockReduceSum(v[0] + v[1] + v[2]) * (1.f / DIM);
    float sq = 0.f;
#pragma unroll
    for (int i = 0; i < 3; i++) { v[i] -= mean; sq += v[i] * v[i]; }
    float var = blockReduceSum(sq) * (1.f / DIM);
    float r = rsqrtf(var + EPSLN);
#pragma unroll
    for (int i = 0; i < 3; i++) {
        int c = tid + i * 256;
        out[(size_t)t * DIM + c] = v[i] * r * g[c] + be[c];
    }
}

// ---------------- launch ----------------
extern "C" void kernel_launch(void* const* d_in, const int* in_sizes, int n_in,
                              void* d_out, int out_size) {
    const float* src  = (const float*)d_in[0];
    const float* Wq = (const float*)d_in[2];
    const float* bq = (const float*)d_in[3];
    const float* Wk = (const float*)d_in[4];
    const float* bk = (const float*)d_in[5];
    const float* Wv = (const float*)d_in[6];
    const float* bv = (const float*)d_in[7];
    const float* Wo = (const float*)d_in[8];
    const float* bo = (const float*)d_in[9];
    const float* gamma = (const float*)d_in[10];
    const float* ln1g = (const float*)d_in[11];
    const float* ln1b = (const float*)d_in[12];
    const float* ln2g = (const float*)d_in[13];
    const float* ln2b = (const float*)d_in[14];
    const float* Wg = (const float*)d_in[15];
    const float* bg = (const float*)d_in[16];
    const float* W1 = (const float*)d_in[17];
    const float* b1 = (const float*)d_in[18];
    const float* W2 = (const float*)d_in[19];
    const float* b2 = (const float*)d_in[20];
    float* out = (float*)d_out;

    float *Qp, *Kp, *attnp, *attnop, *xp;
    cudaGetSymbolAddress((void**)&Qp, g_Q);
    cudaGetSymbolAddress((void**)&Kp, g_K);
    cudaGetSymbolAddress((void**)&attnp, g_attn);
    cudaGetSymbolAddress((void**)&attnop, g_attno);
    cudaGetSymbolAddress((void**)&xp, g_x);

    // zero stats + routing counters
    zero_stats_kernel<<<(ROWS_TOT + 255) / 256, 256>>>();

    // fused QKV projections (V written transposed)
    qkv_mma<<<dim3(DIM / 128, NTOK / 128, 3), 256>>>(src, Wq, bq, Wk, bk, Wv, bv);

    // logits = scale * Q K^T  (+ per-row stats)
    qk_mma<<<dim3(SEQ / 128, SEQ / 128, BHZ), 256>>>(Qp, Kp, 0.125f);

    // per-row zscore coefficients
    finalize_rows<<<(ROWS_TOT + 255) / 256, 256>>>(gamma);

    // fused zscore+softmax+PV
    pv2_mma<<<dim3(1, SEQ / 128, BHZ), 256>>>();

    // O projection
    oproj_mma<<<dim3(DIM / 128, NTOK / 128), 256>>>(attnp, Wo, bo, attnop);

    // x = LN1(src + attn_out), fused gating + routing
    add_ln1_gate_kernel<<<NTOK, 256>>>(src, attnop, ln1g, ln1b, Wg, bg, xp);

    // expert FFN (sparse top-2, TN weights)
    ff1_mma<<<dim3(FFD / 128, NTOK / 128, NE), 256>>>(xp, W1, b1);
    ff2_mma<<<dim3(DIM / 128, NTOK / 128, NE), 256>>>(W2, b2);

    // out = LN2(x + combine(Y))
    add_ln2_moe_kernel<<<NTOK, 256>>>(xp, ln2g, ln2b, out);
}

// round 8
// speedup vs baseline: 1.0991x; 1.0391x over previous
#include <cuda_runtime.h>
#include <math.h>
#include <stdint.h>

// ---------------- problem constants ----------------
namespace {
constexpr int BATCH = 2;
constexpr int SEQ   = 1024;
constexpr int DIM   = 768;
constexpr int NH    = 12;
constexpr int HD    = 64;
constexpr int FFD   = 3072;
constexpr int NE    = 4;
constexpr int NTOK  = BATCH * SEQ;     // 2048
constexpr int BHZ   = BATCH * NH;      // 24
constexpr int ROWS_TOT = BHZ * SEQ;    // 24576 attention rows
constexpr float EPSZ  = 1e-5f;
constexpr float EPSLN = 1e-5f;
}

// ---------------- scratch (static device memory) ----------------
__device__ __align__(16) float g_Q[NTOK * DIM];
__device__ __align__(16) float g_K[NTOK * DIM];
__device__ __align__(16) float g_Vt[BHZ * HD * SEQ];          // V^T: [b][h][d][t]
__device__ __align__(16) float g_P[(size_t)BHZ * SEQ * SEQ];  // raw scaled logits
__device__ __align__(16) float g_attn[NTOK * DIM];
__device__ __align__(16) float g_attno[NTOK * DIM];
__device__ __align__(16) float g_x[NTOK * DIM];
__device__ __align__(16) float g_H1[(size_t)NE * NTOK * FFD];
__device__ __align__(16) float g_Y[(size_t)NE * NTOK * DIM];
__device__ float g_rsum[ROWS_TOT];
__device__ float g_rsumsq[ROWS_TOT];
__device__ unsigned g_rmaxe[ROWS_TOT];
__device__ unsigned g_rmine[ROWS_TOT];
__device__ int   g_cnt[NE];
__device__ int   g_list[NE * NTOK];
__device__ int   g_tslot[2 * NTOK];
__device__ float g_tw[2 * NTOK];

// ---------------- primitives ----------------
__device__ __forceinline__ void mma_op(float* d, const uint32_t* a, uint32_t b0, uint32_t b1) {
    asm volatile(
        "mma.sync.aligned.m16n8k8.row.col.f32.tf32.tf32.f32 "
        "{%0,%1,%2,%3},{%4,%5,%6,%7},{%8,%9},{%0,%1,%2,%3};\n"
        : "+f"(d[0]), "+f"(d[1]), "+f"(d[2]), "+f"(d[3])
        : "r"(a[0]), "r"(a[1]), "r"(a[2]), "r"(a[3]), "r"(b0), "r"(b1));
}
__device__ __forceinline__ void cp_async16(float* dst, const float* src, int sz) {
    uint32_t s = (uint32_t)__cvta_generic_to_shared(dst);
    asm volatile("cp.async.cg.shared.global [%0], [%1], 16, %2;\n"
                 :: "r"(s), "l"(src), "r"(sz));
}
// swizzled float index in a (rows x 16f) tile (A operand / NT B operand)
__device__ __forceinline__ int swz(int row, int col) {
    return (row << 4) + (((((col >> 2) ^ ((row >> 1) & 3))) << 2) | (col & 3));
}
// swizzled index in a TN B tile (16 k-rows x 128 n floats)
__device__ __forceinline__ int swzt(int k, int n) {
    return (k << 7) + ((((n >> 2) ^ ((k & 3) << 1)) << 2) | (n & 3));
}
// ordered-uint encode for float atomic max/min
__device__ __forceinline__ unsigned fenc(float f) {
    unsigned u = __float_as_uint(f);
    return (u & 0x80000000u) ? ~u : (u | 0x80000000u);
}
__device__ __forceinline__ float fdec(unsigned u) {
    unsigned b = (u & 0x80000000u) ? (u ^ 0x80000000u) : ~u;
    return __uint_as_float(b);
}

// ---------------- cp.async 3-stage pipelined tf32 MMA core ----------------
// BM=128, BK=16, 256 threads. BN=128: warps 2x4, MT=4. BN=64: warps 4x2, MT=2.
// BT=0: pb1/pb2 per-thread B row pointers ([N,K] K-contig).
// BT=1: pb1 = B + n0 ([K,N] N-contig), stride ldbt.
template<int BN, int BT>
__device__ __forceinline__ void mma_core(
    const float* pa1, int sa1, const float* pa2, int sa2,
    const float* pb1, const float* pb2, int ldbt,
    int K, float* smem, float (&acc)[(BN == 128) ? 4 : 2][4][4])
{
    constexpr int MT  = (BN == 128) ? 4 : 2;
    constexpr int WN  = (BN == 128) ? 4 : 2;
    constexpr int ASZ = 128 * 16;
    constexpr int BSZ = BN * 16;
    constexpr int STG = ASZ + BSZ;
    const int tid = threadIdx.x;
    const int lane = tid & 31, wid = tid >> 5;
    const int wm = wid / WN, wn = wid % WN;
    const int gid = lane >> 2, tig = lane & 3;
    const int crow = tid >> 2, cq = tid & 3;
    const int coff  = (crow << 4) + ((cq ^ ((crow >> 1) & 3)) << 2);
    const int coff2 = ((crow + 64) << 4) + ((cq ^ ((crow >> 1) & 3)) << 2);
    const int q4 = 4 * cq;
    const int kk = tid >> 4, ng = tid & 15;           // BT mode
    const int bco1 = swzt(kk, 4 * ng);
    const int bco2 = swzt(kk, 4 * (ng + 16));

    auto issue = [&](int i) {
        float* As = smem + (i % 3) * STG;
        float* Bs = As + ASZ;
        const int kt = i << 4;
        cp_async16(As + coff,  pa1 + kt + q4, sa1);
        cp_async16(As + coff2, pa2 + kt + q4, sa2);
        if (BT) {
            const float* bp = pb1 + (size_t)(kt + kk) * ldbt;
            cp_async16(Bs + bco1, bp + 4 * ng, 16);
            cp_async16(Bs + bco2, bp + 4 * ng + 64, 16);
        } else {
            cp_async16(Bs + coff,  pb1 + kt + q4, 16);
            if (BN == 128) cp_async16(Bs + coff2, pb2 + kt + q4, 16);
        }
        asm volatile("cp.async.commit_group;\n" ::: "memory");
    };
    auto compute = [&](int s) {
        const float* As = smem + s * STG;
        const float* Bs = As + ASZ;
#pragma unroll
        for (int c = 0; c < 2; c++) {
            const int k0 = c * 8 + tig;
            uint32_t af[MT][4];
#pragma unroll
            for (int mt = 0; mt < MT; mt++) {
                const int ar = wm * (MT * 16) + mt * 16 + gid;
                af[mt][0] = __float_as_uint(As[swz(ar, k0)]);
                af[mt][1] = __float_as_uint(As[swz(ar + 8, k0)]);
                af[mt][2] = __float_as_uint(As[swz(ar, k0 + 4)]);
                af[mt][3] = __float_as_uint(As[swz(ar + 8, k0 + 4)]);
            }
#pragma unroll
            for (int nt = 0; nt < 4; nt++) {
                const int br = wn * 32 + nt * 8 + gid;
                uint32_t b0, b1;
                if (BT) {
                    b0 = __float_as_uint(Bs[swzt(k0, br)]);
                    b1 = __float_as_uint(Bs[swzt(k0 + 4, br)]);
                } else {
                    b0 = __float_as_uint(Bs[swz(br, k0)]);
                    b1 = __float_as_uint(Bs[swz(br, k0 + 4)]);
                }
#pragma unroll
                for (int mt = 0; mt < MT; mt++) mma_op(acc[mt][nt], af[mt], b0, b1);
            }
        }
    };

    const int nk = K >> 4;
    issue(0);
    if (nk > 1) issue(1);
    for (int i = 0; i < nk; i++) {
        if (i + 1 < nk) asm volatile("cp.async.wait_group 1;\n" ::: "memory");
        else            asm volatile("cp.async.wait_group 0;\n" ::: "memory");
        __syncthreads();
        if (i + 2 < nk) issue(i + 2);
        compute(i % 3);
    }
}

// ---------------- fused QKV projection (z: 0=Q,1=K,2=V-transposed) ----------------
__global__ __launch_bounds__(256, 2) void qkv_mma(
    const float* __restrict__ A,
    const float* __restrict__ Wq, const float* __restrict__ bq,
    const float* __restrict__ Wk, const float* __restrict__ bk,
    const float* __restrict__ Wv, const float* __restrict__ bv)
{
    __shared__ float smem[3 * (128 * 16 + 128 * 16)];
    const int tid = threadIdx.x;
    const int lane = tid & 31, wid = tid >> 5;
    const int wm = wid / 4, wn = wid % 4;
    const int gid = lane >> 2, tig = lane & 3;
    const int crow = tid >> 2;
    float acc[4][4][4] = {};
    const int which = blockIdx.z;
    const float* W = (which == 0) ? Wq : (which == 1) ? Wk : Wv;
    const float* bias = (which == 0) ? bq : (which == 1) ? bk : bv;
    const int m0 = blockIdx.y * 128, n0 = blockIdx.x * 128;
    mma_core<128, 0>(A + (size_t)(m0 + crow) * DIM, 16,
                     A + (size_t)(m0 + crow + 64) * DIM, 16,
                     W + (size_t)(n0 + crow) * DIM,
                     W + (size_t)(n0 + crow + 64) * DIM, 0,
                     DIM, smem, acc);
#pragma unroll
    for (int mt = 0; mt < 4; mt++) {
#pragma unroll
        for (int nt = 0; nt < 4; nt++) {
            int row = m0 + wm * 64 + mt * 16 + gid;
            int col = n0 + wn * 32 + nt * 8 + 2 * tig;
            float c0 = acc[mt][nt][0] + bias[col];
            float c1 = acc[mt][nt][1] + bias[col + 1];
            float c2 = acc[mt][nt][2] + bias[col];
            float c3 = acc[mt][nt][3] + bias[col + 1];
            if (which == 0) {
                *(float2*)(g_Q + (size_t)row * DIM + col) = make_float2(c0, c1);
                *(float2*)(g_Q + (size_t)(row + 8) * DIM + col) = make_float2(c2, c3);
            } else if (which == 1) {
                *(float2*)(g_K + (size_t)row * DIM + col) = make_float2(c0, c1);
                *(float2*)(g_K + (size_t)(row + 8) * DIM + col) = make_float2(c2, c3);
            } else {
                float vals[4] = {c0, c1, c2, c3};
#pragma unroll
                for (int q = 0; q < 4; q++) {
                    int rr = row + (q >> 1) * 8;
                    int cc = col + (q & 1);
                    int bb = rr >> 10, tt = rr & 1023;
                    int h = cc >> 6, d = cc & 63;
                    g_Vt[(((size_t)bb * NH + h) * HD + d) * SEQ + tt] = vals[q];
                }
            }
        }
    }
}

// ---------------- O projection ----------------
__global__ __launch_bounds__(256, 2) void oproj_mma(
    const float* __restrict__ A, const float* __restrict__ W,
    const float* __restrict__ bias, float* __restrict__ C)
{
    __shared__ float smem[3 * (128 * 16 + 128 * 16)];
    const int tid = threadIdx.x;
    const int lane = tid & 31, wid = tid >> 5;
    const int wm = wid / 4, wn = wid % 4;
    const int gid = lane >> 2, tig = lane & 3;
    const int crow = tid >> 2;
    float acc[4][4][4] = {};
    const int m0 = blockIdx.y * 128, n0 = blockIdx.x * 128;
    mma_core<128, 0>(A + (size_t)(m0 + crow) * DIM, 16,
                     A + (size_t)(m0 + crow + 64) * DIM, 16,
                     W + (size_t)(n0 + crow) * DIM,
                     W + (size_t)(n0 + crow + 64) * DIM, 0,
                     DIM, smem, acc);
#pragma unroll
    for (int mt = 0; mt < 4; mt++) {
#pragma unroll
        for (int nt = 0; nt < 4; nt++) {
            int row = m0 + wm * 64 + mt * 16 + gid;
            int col = n0 + wn * 32 + nt * 8 + 2 * tig;
            float b0 = bias[col], b1 = bias[col + 1];
            *(float2*)(C + (size_t)row * DIM + col) =
                make_float2(acc[mt][nt][0] + b0, acc[mt][nt][1] + b1);
            *(float2*)(C + (size_t)(row + 8) * DIM + col) =
                make_float2(acc[mt][nt][2] + b0, acc[mt][nt][3] + b1);
        }
    }
}

// ---------------- QK^T + per-row stats epilogue ----------------
__global__ __launch_bounds__(256, 2) void qk_mma(
    const float* __restrict__ Q, const float* __restrict__ Kt, float scale)
{
    __shared__ float smem[3 * (128 * 16 + 128 * 16)];
    const int tid = threadIdx.x;
    const int lane = tid & 31, wid = tid >> 5;
    const int wm = wid / 4, wn = wid % 4;
    const int gid = lane >> 2, tig = lane & 3;
    const int crow = tid >> 2;
    float acc[4][4][4] = {};
    const int z = blockIdx.z, b = z / NH, h = z % NH;
    const int m0 = blockIdx.y * 128, n0 = blockIdx.x * 128;
    const float* Ab = Q + (size_t)b * SEQ * DIM + h * HD;
    const float* Bb = Kt + (size_t)b * SEQ * DIM + h * HD;
    float* Cb = g_P + (size_t)z * SEQ * SEQ;
    mma_core<128, 0>(Ab + (size_t)(m0 + crow) * DIM, 16,
                     Ab + (size_t)(m0 + crow + 64) * DIM, 16,
                     Bb + (size_t)(n0 + crow) * DIM,
                     Bb + (size_t)(n0 + crow + 64) * DIM, 0,
                     HD, smem, acc);
    const size_t rowbase = (size_t)z * SEQ + m0;
#pragma unroll
    for (int mt = 0; mt < 4; mt++) {
        float s0 = 0.f, q0 = 0.f, s8 = 0.f, q8 = 0.f;
        float mx0 = -3e38f, mn0 = 3e38f, mx8 = -3e38f, mn8 = 3e38f;
#pragma unroll
        for (int nt = 0; nt < 4; nt++) {
            int row = m0 + wm * 64 + mt * 16 + gid;
            int col = n0 + wn * 32 + nt * 8 + 2 * tig;
            float v0 = acc[mt][nt][0] * scale, v1 = acc[mt][nt][1] * scale;
            float v2 = acc[mt][nt][2] * scale, v3 = acc[mt][nt][3] * scale;
            *(float2*)(Cb + (size_t)row * SEQ + col) = make_float2(v0, v1);
            *(float2*)(Cb + (size_t)(row + 8) * SEQ + col) = make_float2(v2, v3);
            s0 += v0 + v1; q0 += v0 * v0 + v1 * v1;
            mx0 = fmaxf(mx0, fmaxf(v0, v1)); mn0 = fminf(mn0, fminf(v0, v1));
            s8 += v2 + v3; q8 += v2 * v2 + v3 * v3;
            mx8 = fmaxf(mx8, fmaxf(v2, v3)); mn8 = fminf(mn8, fminf(v2, v3));
        }
#pragma unroll
        for (int o = 1; o < 4; o <<= 1) {
            s0 += __shfl_xor_sync(~0u, s0, o); q0 += __shfl_xor_sync(~0u, q0, o);
            s8 += __shfl_xor_sync(~0u, s8, o); q8 += __shfl_xor_sync(~0u, q8, o);
            mx0 = fmaxf(mx0, __shfl_xor_sync(~0u, mx0, o));
            mn0 = fminf(mn0, __shfl_xor_sync(~0u, mn0, o));
            mx8 = fmaxf(mx8, __shfl_xor_sync(~0u, mx8, o));
            mn8 = fminf(mn8, __shfl_xor_sync(~0u, mn8, o));
        }
        if (tig == 0) {
            size_t r0 = rowbase + wm * 64 + mt * 16 + gid;
            atomicAdd(&g_rsum[r0], s0);   atomicAdd(&g_rsumsq[r0], q0);
            atomicMax(&g_rmaxe[r0], fenc(mx0)); atomicMin(&g_rmine[r0], fenc(mn0));
            atomicAdd(&g_rsum[r0 + 8], s8); atomicAdd(&g_rsumsq[r0 + 8], q8);
            atomicMax(&g_rmaxe[r0 + 8], fenc(mx8)); atomicMin(&g_rmine[r0 + 8], fenc(mn8));
        }
    }
}

// ---------------- zero stats + routing counters ----------------
__global__ void zero_stats_kernel() {
    int i = blockIdx.x * 256 + threadIdx.x;
    if (i < ROWS_TOT) {
        g_rsum[i] = 0.f;
        g_rsumsq[i] = 0.f;
        g_rmaxe[i] = fenc(-3e38f);
        g_rmine[i] = fenc(3e38f);
    }
    if (i < NE) g_cnt[i] = 0;
}

// ---------------- fused zscore-softmax + P@V (rowc computed in prologue) ----------------
__global__ __launch_bounds__(256, 2) void pv2_mma(const float* __restrict__ gamma)
{
    __shared__ float Asm[2][128 * 16];
    __shared__ float Bsm[3][64 * 16];
    __shared__ float denom_s[128];
    __shared__ float2 rowc_s[128];
    const int tid = threadIdx.x;
    const int lane = tid & 31, wid = tid >> 5;
    const int wm = wid / 2, wn = wid % 2;
    const int gid = lane >> 2, tig = lane & 3;
    const int crow = tid >> 2, cq = tid & 3;
    const int coff  = (crow << 4) + ((cq ^ ((crow >> 1) & 3)) << 2);
    const int coff2 = ((crow + 64) << 4) + ((cq ^ ((crow >> 1) & 3)) << 2);
    const int q4 = 4 * cq;
    float acc[2][4][4] = {};
    const int z = blockIdx.z, b = z / NH, h = z % NH;
    const int m0 = blockIdx.y * 128;
    const float* Arow1 = g_P + ((size_t)z * SEQ + m0 + crow) * SEQ;
    const float* Arow2 = g_P + ((size_t)z * SEQ + m0 + crow + 64) * SEQ;
    const float* Brow = g_Vt + (size_t)z * HD * SEQ + (size_t)crow * SEQ;
    float esum1 = 0.f, esum2 = 0.f;
    constexpr int nk = SEQ / 16;  // 64

    auto issueB = [&](int i) {
        cp_async16(Bsm[i % 3] + coff, Brow + (i << 4) + q4, 16);
        asm volatile("cp.async.commit_group;\n" ::: "memory");
    };
    auto compute = [&](const float* As, const float* Bs) {
#pragma unroll
        for (int c = 0; c < 2; c++) {
            const int k0 = c * 8 + tig;
            uint32_t af[2][4];
#pragma unroll
            for (int mt = 0; mt < 2; mt++) {
                const int ar = wm * 32 + mt * 16 + gid;
                af[mt][0] = __float_as_uint(As[swz(ar, k0)]);
                af[mt][1] = __float_as_uint(As[swz(ar + 8, k0)]);
                af[mt][2] = __float_as_uint(As[swz(ar, k0 + 4)]);
                af[mt][3] = __float_as_uint(As[swz(ar + 8, k0 + 4)]);
            }
#pragma unroll
            for (int nt = 0; nt < 4; nt++) {
                const int br = wn * 32 + nt * 8 + gid;
                uint32_t b0 = __float_as_uint(Bs[swz(br, k0)]);
                uint32_t b1 = __float_as_uint(Bs[swz(br, k0 + 4)]);
#pragma unroll
                for (int mt = 0; mt < 2; mt++) mma_op(acc[mt][nt], af[mt], b0, b1);
            }
        }
    };

    issueB(0);
    issueB(1);
    // fold finalize: compute per-row zscore coefficients locally
    if (tid < 128) {
        size_t i = (size_t)z * SEQ + m0 + tid;
        float s = g_rsum[i], q = g_rsumsq[i];
        float mean = s * (1.f / SEQ);
        float var = fmaxf((q - s * s * (1.f / SEQ)) * (1.f / (SEQ - 1)), 0.f);
        float c1 = (*gamma) / (sqrtf(var) + EPSZ);
        float mx = fdec(g_rmaxe[i]), mn = fdec(g_rmine[i]);
        float zmax = fmaxf(c1 * (mx - mean), c1 * (mn - mean));
        rowc_s[tid] = make_float2(c1, -mean * c1 - zmax);
    }
    __syncthreads();
    const float2 rc1 = rowc_s[crow];
    const float2 rc2 = rowc_s[crow + 64];
    float4 a0 = *(const float4*)(Arow1 + q4);
    float4 a1 = *(const float4*)(Arow2 + q4);
    for (int i = 0; i < nk; i++) {
        if (i + 1 < nk) asm volatile("cp.async.wait_group 1;\n" ::: "memory");
        else            asm volatile("cp.async.wait_group 0;\n" ::: "memory");
        __syncthreads();                       // B(i) visible; compute(i-1) done
        if (i + 2 < nk) issueB(i + 2);
        float4 e0, e1;
        e0.x = __expf(fmaf(a0.x, rc1.x, rc1.y));
        e0.y = __expf(fmaf(a0.y, rc1.x, rc1.y));
        e0.z = __expf(fmaf(a0.z, rc1.x, rc1.y));
        e0.w = __expf(fmaf(a0.w, rc1.x, rc1.y));
        e1.x = __expf(fmaf(a1.x, rc2.x, rc2.y));
        e1.y = __expf(fmaf(a1.y, rc2.x, rc2.y));
        e1.z = __expf(fmaf(a1.z, rc2.x, rc2.y));
        e1.w = __expf(fmaf(a1.w, rc2.x, rc2.y));
        esum1 += e0.x + e0.y + e0.z + e0.w;
        esum2 += e1.x + e1.y + e1.z + e1.w;
        *(float4*)(Asm[i & 1] + coff)  = e0;
        *(float4*)(Asm[i & 1] + coff2) = e1;
        if (i + 1 < nk) {                      // prefetch next A tile
            a0 = *(const float4*)(Arow1 + ((i + 1) << 4) + q4);
            a1 = *(const float4*)(Arow2 + ((i + 1) << 4) + q4);
        }
        __syncthreads();                       // A STS visible
        compute(Asm[i & 1], Bsm[i % 3]);
    }
    // row exp-sums -> denominators
#pragma unroll
    for (int o = 1; o < 4; o <<= 1) {
        esum1 += __shfl_xor_sync(~0u, esum1, o);
        esum2 += __shfl_xor_sync(~0u, esum2, o);
    }
    if ((tid & 3) == 0) {
        denom_s[crow] = esum1;
        denom_s[crow + 64] = esum2;
    }
    __syncthreads();
#pragma unroll
    for (int mt = 0; mt < 2; mt++) {
#pragma unroll
        for (int nt = 0; nt < 4; nt++) {
            int ro = wm * 32 + mt * 16 + gid;
            int col = wn * 32 + nt * 8 + 2 * tig;
            float r0 = 1.f / denom_s[ro];
            float r8 = 1.f / denom_s[ro + 8];
            int row = m0 + ro;
            float* c0 = g_attn + ((size_t)(b * SEQ + row)) * DIM + h * HD + col;
            float* c1 = g_attn + ((size_t)(b * SEQ + row + 8)) * DIM + h * HD + col;
            *(float2*)c0 = make_float2(acc[mt][nt][0] * r0, acc[mt][nt][1] * r0);
            *(float2*)c1 = make_float2(acc[mt][nt][2] * r8, acc[mt][nt][3] * r8);
        }
    }
}

// ---------------- FF1 (TN): H1 = relu(x[list] @ W1[e] + b1) ----------------
__global__ __launch_bounds__(256, 2) void ff1_mma(
    const float* __restrict__ x, const float* __restrict__ W1,
    const float* __restrict__ b1)
{
    const int e = blockIdx.z;
    const int cnt = g_cnt[e];
    const int m0 = blockIdx.y * 128;
    if (m0 >= cnt) return;
    __shared__ float smem[3 * (128 * 16 + 128 * 16)];
    const int tid = threadIdx.x;
    const int lane = tid & 31, wid = tid >> 5;
    const int wm = wid / 4, wn = wid % 4;
    const int gid = lane >> 2, tig = lane & 3;
    const int crow = tid >> 2;
    float acc[4][4][4] = {};
    const int n0 = blockIdx.x * 128;
    const int r1 = m0 + crow, r2 = m0 + crow + 64;
    const float* pa1 = x; int sa1 = 0;
    const float* pa2 = x; int sa2 = 0;
    if (r1 < cnt) { pa1 = x + (size_t)g_list[e * NTOK + r1] * DIM; sa1 = 16; }
    if (r2 < cnt) { pa2 = x + (size_t)g_list[e * NTOK + r2] * DIM; sa2 = 16; }
    const float* Bb = W1 + (size_t)e * DIM * FFD + n0;   // [K=DIM][N=FFD]
    const float* bb = b1 + e * FFD;
    float* Hout = g_H1 + (size_t)e * NTOK * FFD;
    mma_core<128, 1>(pa1, sa1, pa2, sa2, Bb, nullptr, FFD, DIM, smem, acc);
#pragma unroll
    for (int mt = 0; mt < 4; mt++) {
#pragma unroll
        for (int nt = 0; nt < 4; nt++) {
            int lm = m0 + wm * 64 + mt * 16 + gid;
            int col = n0 + wn * 32 + nt * 8 + 2 * tig;
            float b0 = bb[col], b1v = bb[col + 1];
            if (lm < cnt) {
                *(float2*)(Hout + (size_t)lm * FFD + col) =
                    make_float2(fmaxf(acc[mt][nt][0] + b0, 0.f), fmaxf(acc[mt][nt][1] + b1v, 0.f));
            }
            if (lm + 8 < cnt) {
                *(float2*)(Hout + (size_t)(lm + 8) * FFD + col) =
                    make_float2(fmaxf(acc[mt][nt][2] + b0, 0.f), fmaxf(acc[mt][nt][3] + b1v, 0.f));
            }
        }
    }
}

// ---------------- FF2 (TN): Y = H1 @ W2[e] + b2 ----------------
__global__ __launch_bounds__(256, 2) void ff2_mma(
    const float* __restrict__ W2, const float* __restrict__ b2)
{
    const int e = blockIdx.z;
    const int cnt = g_cnt[e];
    const int m0 = blockIdx.y * 128;
    if (m0 >= cnt) return;
    __shared__ float smem[3 * (128 * 16 + 128 * 16)];
    const int tid = threadIdx.x;
    const int lane = tid & 31, wid = tid >> 5;
    const int wm = wid / 4, wn = wid % 4;
    const int gid = lane >> 2, tig = lane & 3;
    const int crow = tid >> 2;
    float acc[4][4][4] = {};
    const int n0 = blockIdx.x * 128;
    const float* Ab = g_H1 + (size_t)e * NTOK * FFD;
    const int r1 = m0 + crow, r2 = m0 + crow + 64;
    const float* pa1 = Ab; int sa1 = 0;
    const float* pa2 = Ab; int sa2 = 0;
    if (r1 < cnt) { pa1 = Ab + (size_t)r1 * FFD; sa1 = 16; }
    if (r2 < cnt) { pa2 = Ab + (size_t)r2 * FFD; sa2 = 16; }
    const float* Bb = W2 + (size_t)e * FFD * DIM + n0;   // [K=FFD][N=DIM]
    const float* bb = b2 + e * DIM;
    float* Yout = g_Y + (size_t)e * NTOK * DIM;
    mma_core<128, 1>(pa1, sa1, pa2, sa2, Bb, nullptr, DIM, FFD, smem, acc);
#pragma unroll
    for (int mt = 0; mt < 4; mt++) {
#pragma unroll
        for (int nt = 0; nt < 4; nt++) {
            int lm = m0 + wm * 64 + mt * 16 + gid;
            int col = n0 + wn * 32 + nt * 8 + 2 * tig;
            float b0 = bb[col], b1v = bb[col + 1];
            if (lm < cnt) {
                *(float2*)(Yout + (size_t)lm * DIM + col) =
                    make_float2(acc[mt][nt][0] + b0, acc[mt][nt][1] + b1v);
            }
            if (lm + 8 < cnt) {
                *(float2*)(Yout + (size_t)(lm + 8) * DIM + col) =
                    make_float2(acc[mt][nt][2] + b0, acc[mt][nt][3] + b1v);
            }
        }
    }
}

// ---------------- reductions ----------------
__device__ __forceinline__ float blockReduceSum(float v) {
    __shared__ float red[8];
    int lane = threadIdx.x & 31, wid = threadIdx.x >> 5;
#pragma unroll
    for (int o = 16; o > 0; o >>= 1) v += __shfl_xor_sync(0xffffffffu, v, o);
    __syncthreads();
    if (lane == 0) red[wid] = v;
    __syncthreads();
    float r = (lane < 8) ? red[lane] : 0.f;
#pragma unroll
    for (int o = 16; o > 0; o >>= 1) r += __shfl_xor_sync(0xffffffffu, r, o);
    return r;
}

// ---------------- LN1 + fused gating ----------------
__global__ void add_ln1_gate_kernel(const float* __restrict__ a, const float* __restrict__ b,
                                    const float* __restrict__ g, const float* __restrict__ be,
                                    const float* __restrict__ Wg, const float* __restrict__ bg,
                                    float* __restrict__ out) {
    int t = blockIdx.x, tid = threadIdx.x;
    const float* ar = a + (size_t)t * DIM;
    const float* br = b + (size_t)t * DIM;
    float v[3];
#pragma unroll
    for (int i = 0; i < 3; i++) v[i] = ar[tid + i * 256] + br[tid + i * 256];
    float mean = blockReduceSum(v[0] + v[1] + v[2]) * (1.f / DIM);
    float sq = 0.f;
#pragma unroll
    for (int i = 0; i < 3; i++) { v[i] -= mean; sq += v[i] * v[i]; }
    float var = blockReduceSum(sq) * (1.f / DIM);
    float r = rsqrtf(var + EPSLN);
    float xv[3];
    float gp0 = 0.f, gp1 = 0.f, gp2 = 0.f, gp3 = 0.f;
#pragma unroll
    for (int i = 0; i < 3; i++) {
        int c = tid + i * 256;
        xv[i] = v[i] * r * g[c] + be[c];
        out[(size_t)t * DIM + c] = xv[i];
        gp0 += xv[i] * Wg[c];
        gp1 += xv[i] * Wg[DIM + c];
        gp2 += xv[i] * Wg[2 * DIM + c];
        gp3 += xv[i] * Wg[3 * DIM + c];
    }
    float s0 = blockReduceSum(gp0);
    float s1 = blockReduceSum(gp1);
    float s2 = blockReduceSum(gp2);
    float s3 = blockReduceSum(gp3);
    if (tid == 0) {
        float s[4] = {s0 + bg[0], s1 + bg[1], s2 + bg[2], s3 + bg[3]};
        float mx = fmaxf(fmaxf(s[0], s[1]), fmaxf(s[2], s[3]));
        float p[4], sum = 0.f;
#pragma unroll
        for (int e = 0; e < 4; e++) { p[e] = expf(s[e] - mx); sum += p[e]; }
        float ri = 1.f / sum;
#pragma unroll
        for (int e = 0; e < 4; e++) p[e] *= ri;
        int i1 = 0;
#pragma unroll
        for (int e = 1; e < 4; e++) if (p[e] > p[i1]) i1 = e;
        int i2 = (i1 == 0) ? 1 : 0;
#pragma unroll
        for (int e = 0; e < 4; e++) if (e != i1 && p[e] > p[i2]) i2 = e;
        int slot = atomicAdd(&g_cnt[i1], 1);
        g_list[i1 * NTOK + slot] = t;
        g_tslot[t] = i1 * NTOK + slot;
        g_tw[t] = p[i1];
        slot = atomicAdd(&g_cnt[i2], 1);
        g_list[i2 * NTOK + slot] = t;
        g_tslot[NTOK + t] = i2 * NTOK + slot;
        g_tw[NTOK + t] = p[i2];
    }
}

// ---------------- LN2 + MoE combine ----------------
__global__ void add_ln2_moe_kernel(const float* __restrict__ x,
                                   const float* __restrict__ g, const float* __restrict__ be,
                                   float* __restrict__ out) {
    int t = blockIdx.x, tid = threadIdx.x;
    int s1 = g_tslot[t], s2 = g_tslot[NTOK + t];
    float w1 = g_tw[t], w2 = g_tw[NTOK + t];
    const float* y1 = g_Y + (size_t)s1 * DIM;
    const float* y2 = g_Y + (size_t)s2 * DIM;
    const float* xr = x + (size_t)t * DIM;
    float v[3];
#pragma unroll
    for (int i = 0; i < 3; i++) {
        int c = tid + i * 256;
        v[i] = xr[c] + w1 * y1[c] + w2 * y2[c];
    }
    float mean = blockReduceSum(v[0] + v[1] + v[2]) * (1.f / DIM);
    float sq = 0.f;
#pragma unroll
    for (int i = 0; i < 3; i++) { v[i] -= mean; sq += v[i] * v[i]; }
    float var = blockReduceSum(sq) * (1.f / DIM);
    float r = rsqrtf(var + EPSLN);
#pragma unroll
    for (int i = 0; i < 3; i++) {
        int c = tid + i * 256;
        out[(size_t)t * DIM + c] = v[i] * r * g[c] + be[c];
    }
}

// ---------------- launch ----------------
extern "C" void kernel_launch(void* const* d_in, const int* in_sizes, int n_in,
                              void* d_out, int out_size) {
    const float* src  = (const float*)d_in[0];
    const float* Wq = (const float*)d_in[2];
    const float* bq = (const float*)d_in[3];
    const float* Wk = (const float*)d_in[4];
    const float* bk = (const float*)d_in[5];
    const float* Wv = (const float*)d_in[6];
    const float* bv = (const float*)d_in[7];
    const float* Wo = (const float*)d_in[8];
    const float* bo = (const float*)d_in[9];
    const float* gamma = (const float*)d_in[10];
    const float* ln1g = (const float*)d_in[11];
    const float* ln1b = (const float*)d_in[12];
    const float* ln2g = (const float*)d_in[13];
    const float* ln2b = (const float*)d_in[14];
    const float* Wg = (const float*)d_in[15];
    const float* bg = (const float*)d_in[16];
    const float* W1 = (const float*)d_in[17];
    const float* b1 = (const float*)d_in[18];
    const float* W2 = (const float*)d_in[19];
    const float* b2 = (const float*)d_in[20];
    float* out = (float*)d_out;

    float *Qp, *Kp, *attnp, *attnop, *xp;
    cudaGetSymbolAddress((void**)&Qp, g_Q);
    cudaGetSymbolAddress((void**)&Kp, g_K);
    cudaGetSymbolAddress((void**)&attnp, g_attn);
    cudaGetSymbolAddress((void**)&attnop, g_attno);
    cudaGetSymbolAddress((void**)&xp, g_x);

    // zero stats + routing counters
    zero_stats_kernel<<<(ROWS_TOT + 255) / 256, 256>>>();

    // fused QKV projections (V written transposed)
    qkv_mma<<<dim3(DIM / 128, NTOK / 128, 3), 256>>>(src, Wq, bq, Wk, bk, Wv, bv);

    // logits = scale * Q K^T  (+ per-row stats)
    qk_mma<<<dim3(SEQ / 128, SEQ / 128, BHZ), 256>>>(Qp, Kp, 0.125f);

    // fused zscore+softmax+PV (rowc computed in prologue)
    pv2_mma<<<dim3(1, SEQ / 128, BHZ), 256>>>(gamma);

    // O projection
    oproj_mma<<<dim3(DIM / 128, NTOK / 128), 256>>>(attnp, Wo, bo, attnop);

    // x = LN1(src + attn_out), fused gating + routing
    add_ln1_gate_kernel<<<NTOK, 256>>>(src, attnop, ln1g, ln1b, Wg, bg, xp);

    // expert FFN (sparse top-2, TN weights)
    ff1_mma<<<dim3(FFD / 128, NTOK / 128, NE), 256>>>(xp, W1, b1);
    ff2_mma<<<dim3(DIM / 128, NTOK / 128, NE), 256>>>(W2, b2);

    // out = LN2(x + combine(Y))
    add_ln2_moe_kernel<<<NTOK, 256>>>(xp, ln2g, ln2b, out);
}